// round 1
// baseline (speedup 1.0000x reference)
#include <cuda_runtime.h>

#define B 8192
#define T 15
#define D 81
#define HE 256
#define NG 1024
#define KENC 337      // 81 (x) + 256 (h)
#define KENC_PAD 352  // 22 * 16
#define KDEC 257      // 1 (y_tilde) + 256 (d)
#define KDEC_PAD 272  // 17 * 16

#define BM 128
#define BN 64
#define BK 16
#define TM 8
#define TN 4

// ---------------- scratch (static device memory; no allocations) ----------
__device__ float g_A1[B * D];
__device__ float g_A12[B * D];
__device__ float g_Wenc[2][KENC_PAD][NG];   // packed: col = m*4 + gate
__device__ float g_benc[2][NG];
__device__ float g_Wdec[KDEC_PAD][NG];
__device__ float g_bdec[NG];
__device__ float g_Wq[512][HE];             // [k][n]: k<256 -> W1d, else W1c
__device__ float g_Wxp[HE][HE];             // [k][n] = W1x[n][k]
__device__ float g_h1[2][B * HE];
__device__ float g_c1[2][B * HE];
__device__ float g_h2[2][B * HE];
__device__ float g_c2[2][B * HE];
__device__ float g_Xenc[B * T * HE];        // [b][t][h]
__device__ float g_xproj[B * T * HE];
__device__ float g_dc[2][B * 512];          // decoder state [d | c]
__device__ float g_q[B * HE];
__device__ float g_yt[B];
__device__ float g_ctx[B * HE];

// ---------------- math helpers -------------------------------------------
__device__ __forceinline__ float sigf(float x) {
    return __fdividef(1.f, 1.f + __expf(-x));
}
__device__ __forceinline__ float ftanh(float x) {
    float e = __expf(-2.f * fabsf(x));
    float r = __fdividef(1.f - e, 1.f + e);
    return copysignf(r, x);
}

// ---------------- weight packing ------------------------------------------
__global__ void pack_kernel(const float* __restrict__ l1_wih, const float* __restrict__ l1_whh,
                            const float* __restrict__ l1_b,
                            const float* __restrict__ l2_wih, const float* __restrict__ l2_whh,
                            const float* __restrict__ l2_b,
                            const float* __restrict__ dl_wih, const float* __restrict__ dl_whh,
                            const float* __restrict__ dl_b,
                            const float* __restrict__ da1w) {
    int stride = gridDim.x * blockDim.x;
    int idx0 = blockIdx.x * blockDim.x + threadIdx.x;
    for (int i = idx0; i < KENC_PAD * NG; i += stride) {
        int k = i >> 10, col = i & 1023;
        int m = col >> 2, g = col & 3;
        int n = g * HE + m;
        float v1 = 0.f, v2 = 0.f;
        if (k < D)         { v1 = l1_wih[n * D + k];        v2 = l2_wih[n * D + k]; }
        else if (k < KENC) { v1 = l1_whh[n * HE + (k - D)]; v2 = l2_whh[n * HE + (k - D)]; }
        g_Wenc[0][k][col] = v1;
        g_Wenc[1][k][col] = v2;
    }
    for (int i = idx0; i < KDEC_PAD * NG; i += stride) {
        int k = i >> 10, col = i & 1023;
        int m = col >> 2, g = col & 3;
        int n = g * HE + m;
        float v = 0.f;
        if (k == 0)        v = dl_wih[n];
        else if (k < KDEC) v = dl_whh[n * HE + (k - 1)];
        g_Wdec[k][col] = v;
    }
    for (int i = idx0; i < 512 * HE; i += stride) {
        int k = i >> 8, n = i & 255;
        g_Wq[k][n] = (k < HE) ? da1w[n * 768 + k] : da1w[n * 768 + 256 + (k - HE)];
    }
    for (int i = idx0; i < HE * HE; i += stride) {
        int k = i >> 8, n = i & 255;
        g_Wxp[k][n] = da1w[n * 768 + 512 + k];
    }
    for (int i = idx0; i < NG; i += stride) {
        int m = i >> 2, g = i & 3;
        int n = g * HE + m;
        g_benc[0][i] = l1_b[n];
        g_benc[1][i] = l2_b[n];
        g_bdec[i]    = dl_b[n];
    }
}

__global__ void init_kernel() {
    int stride = gridDim.x * blockDim.x;
    int i0 = blockIdx.x * blockDim.x + threadIdx.x;
    for (int j = i0; j < B * HE; j += stride) {
        g_h1[0][j] = 0.f; g_c1[0][j] = 0.f;
        g_h2[0][j] = 0.f; g_c2[0][j] = 0.f;
    }
    for (int j = i0; j < B * 512; j += stride) g_dc[0][j] = 0.f;
}

// ---------------- input attention (a1, a1*a2) — state-independent ---------
__global__ void attn_kernel(const float* __restrict__ X, const float* __restrict__ yprev,
                            const float* __restrict__ e1w, const float* __restrict__ e1b,
                            const float* __restrict__ e2w, const float* __restrict__ e2b) {
    int b = blockIdx.x;
    int j = threadIdx.x;
    float v1 = -1e30f, v2 = -1e30f;
    if (j < D) {
        const float* xb = X + (size_t)b * T * D + j;
        float s1 = 0.f, s2 = 0.f;
#pragma unroll
        for (int t = 0; t < T; ++t) {
            float x = xb[t * D];
            s1 += x * e1w[2 * HE + t];
            s2 += x * e2w[2 * HE + t];
        }
        float yw = 0.f;
#pragma unroll
        for (int t = 0; t < T; ++t) yw += yprev[b * T + t] * e2w[2 * HE + T + t];
        v1 = s1 + e1b[0];
        v2 = s2 + yw + e2b[0];
    }
    __shared__ float red1[128], red2[128];
    red1[j] = v1; red2[j] = v2;
    __syncthreads();
    for (int o = 64; o > 0; o >>= 1) {
        if (j < o) {
            red1[j] = fmaxf(red1[j], red1[j + o]);
            red2[j] = fmaxf(red2[j], red2[j + o]);
        }
        __syncthreads();
    }
    float m1 = red1[0], m2 = red2[0];
    __syncthreads();
    float e1v = (j < D) ? __expf(v1 - m1) : 0.f;
    float e2v = (j < D) ? __expf(v2 - m2) : 0.f;
    red1[j] = e1v; red2[j] = e2v;
    __syncthreads();
    for (int o = 64; o > 0; o >>= 1) {
        if (j < o) { red1[j] += red1[j + o]; red2[j] += red2[j + o]; }
        __syncthreads();
    }
    if (j < D) {
        float a1 = __fdividef(e1v, red1[0]);
        float a2 = __fdividef(e2v, red2[0]);
        g_A1[b * D + j]  = a1;
        g_A12[b * D + j] = a1 * a2;
    }
}

// ---------------- encoder step: fused [x|h] GEMM + LSTM epilogue ----------
__global__ __launch_bounds__(256) void enc_step_kernel(const float* __restrict__ X, int t,
                                                       int pin, int pout) {
    int L = blockIdx.z;
    const float* scale = L ? g_A12 : g_A1;
    const float* hin = L ? g_h2[pin] : g_h1[pin];
    const float* cin = L ? g_c2[pin] : g_c1[pin];
    float* hout = L ? g_h2[pout] : g_h1[pout];
    float* cout = L ? g_c2[pout] : g_c1[pout];
    const float(*W)[NG] = g_Wenc[L];
    const float* bias = g_benc[L];

    __shared__ float As[BK][BM + 4];
    __shared__ float Bs[BK][BN];

    int tid = threadIdx.x;
    int tx = tid & 15, ty = tid >> 4;
    int row0 = blockIdx.x * BM;
    int col0 = blockIdx.y * BN;
    int lk = tid & 15, lr = tid >> 4;
    int bc = tid & 63, bk0 = tid >> 6;

    float acc[TM][TN] = {};

    for (int kc = 0; kc < KENC_PAD / BK; ++kc) {
        int kbase = kc * BK;
        int k = kbase + lk;
#pragma unroll
        for (int i = 0; i < 8; ++i) {
            int r = lr + 16 * i;
            int gb = row0 + r;
            float v;
            if (k < D)         v = scale[gb * D + k] * X[(size_t)gb * (T * D) + t * D + k];
            else if (k < KENC) v = hin[gb * HE + (k - D)];
            else               v = 0.f;
            As[lk][r] = v;
        }
#pragma unroll
        for (int j = 0; j < 4; ++j) {
            int kk = bk0 + 4 * j;
            Bs[kk][bc] = W[kbase + kk][col0 + bc];
        }
        __syncthreads();
#pragma unroll
        for (int kk = 0; kk < BK; ++kk) {
            float a[TM], bb[TN];
#pragma unroll
            for (int i = 0; i < TM; ++i) a[i] = As[kk][ty * TM + i];
#pragma unroll
            for (int j = 0; j < TN; ++j) bb[j] = Bs[kk][tx * TN + j];
#pragma unroll
            for (int i = 0; i < TM; ++i)
#pragma unroll
                for (int j = 0; j < TN; ++j) acc[i][j] += a[i] * bb[j];
        }
        __syncthreads();
    }

    int m = (col0 >> 2) + tx;  // hidden unit index
    float bi = bias[col0 + tx * 4 + 0];
    float bf = bias[col0 + tx * 4 + 1];
    float bg = bias[col0 + tx * 4 + 2];
    float bo = bias[col0 + tx * 4 + 3];
#pragma unroll
    for (int i = 0; i < TM; ++i) {
        int gb = row0 + ty * TM + i;
        float gi = acc[i][0] + bi;
        float gf = acc[i][1] + bf;
        float gg = acc[i][2] + bg;
        float go = acc[i][3] + bo;
        float cold = cin[gb * HE + m];
        float c2 = sigf(gf) * cold + sigf(gi) * ftanh(gg);
        float h2 = sigf(go) * ftanh(c2);
        hout[gb * HE + m] = h2;
        cout[gb * HE + m] = c2;
        if (L) g_Xenc[((size_t)gb * T + t) * HE + m] = h2;
    }
}

// ---------------- decoder LSTM: fused [y_tilde|d] GEMM + LSTM epilogue ----
__global__ __launch_bounds__(256) void dec_lstm_kernel(int pin, int pout) {
    const float* dcin = g_dc[pin];
    float* dcout = g_dc[pout];

    __shared__ float As[BK][BM + 4];
    __shared__ float Bs[BK][BN];

    int tid = threadIdx.x;
    int tx = tid & 15, ty = tid >> 4;
    int row0 = blockIdx.x * BM;
    int col0 = blockIdx.y * BN;
    int lk = tid & 15, lr = tid >> 4;
    int bc = tid & 63, bk0 = tid >> 6;

    float acc[TM][TN] = {};

    for (int kc = 0; kc < KDEC_PAD / BK; ++kc) {
        int kbase = kc * BK;
        int k = kbase + lk;
#pragma unroll
        for (int i = 0; i < 8; ++i) {
            int r = lr + 16 * i;
            int gb = row0 + r;
            float v;
            if (k == 0)        v = g_yt[gb];
            else if (k < KDEC) v = dcin[gb * 512 + (k - 1)];
            else               v = 0.f;
            As[lk][r] = v;
        }
#pragma unroll
        for (int j = 0; j < 4; ++j) {
            int kk = bk0 + 4 * j;
            Bs[kk][bc] = g_Wdec[kbase + kk][col0 + bc];
        }
        __syncthreads();
#pragma unroll
        for (int kk = 0; kk < BK; ++kk) {
            float a[TM], bb[TN];
#pragma unroll
            for (int i = 0; i < TM; ++i) a[i] = As[kk][ty * TM + i];
#pragma unroll
            for (int j = 0; j < TN; ++j) bb[j] = Bs[kk][tx * TN + j];
#pragma unroll
            for (int i = 0; i < TM; ++i)
#pragma unroll
                for (int j = 0; j < TN; ++j) acc[i][j] += a[i] * bb[j];
        }
        __syncthreads();
    }

    int m = (col0 >> 2) + tx;
    float bi = g_bdec[col0 + tx * 4 + 0];
    float bf = g_bdec[col0 + tx * 4 + 1];
    float bg = g_bdec[col0 + tx * 4 + 2];
    float bo = g_bdec[col0 + tx * 4 + 3];
#pragma unroll
    for (int i = 0; i < TM; ++i) {
        int gb = row0 + ty * TM + i;
        float gi = acc[i][0] + bi;
        float gf = acc[i][1] + bf;
        float gg = acc[i][2] + bg;
        float go = acc[i][3] + bo;
        float cold = dcin[gb * 512 + 256 + m];
        float c2 = sigf(gf) * cold + sigf(gi) * ftanh(gg);
        float h2 = sigf(go) * ftanh(c2);
        dcout[gb * 512 + m] = h2;
        dcout[gb * 512 + 256 + m] = c2;
    }
}

// ---------------- plain GEMM, N=256 (xenc_proj and q) ---------------------
// mode 0: xproj = Xenc @ Wxp + da1b   (M = B*T, K = 256)
// mode 1: q     = [d|c] @ Wq          (M = B,   K = 512)
__global__ __launch_bounds__(256) void gemm256_kernel(int mode, int pin,
                                                      const float* __restrict__ bias) {
    const float* Aptr;
    const float* Wptr;
    float* Cptr;
    int lda, nkc;
    if (mode == 0) { Aptr = g_Xenc;    Wptr = &g_Wxp[0][0]; Cptr = g_xproj; lda = 256; nkc = 16; }
    else           { Aptr = g_dc[pin]; Wptr = &g_Wq[0][0];  Cptr = g_q;     lda = 512; nkc = 32; }

    __shared__ float As[BK][BM + 4];
    __shared__ float Bs[BK][BN];

    int tid = threadIdx.x;
    int tx = tid & 15, ty = tid >> 4;
    int row0 = blockIdx.x * BM;
    int col0 = blockIdx.y * BN;
    int lk = tid & 15, lr = tid >> 4;
    int bc = tid & 63, bk0 = tid >> 6;

    float acc[TM][TN] = {};

    for (int kc = 0; kc < nkc; ++kc) {
        int kbase = kc * BK;
#pragma unroll
        for (int i = 0; i < 8; ++i) {
            int r = lr + 16 * i;
            As[lk][r] = Aptr[(size_t)(row0 + r) * lda + kbase + lk];
        }
#pragma unroll
        for (int j = 0; j < 4; ++j) {
            int kk = bk0 + 4 * j;
            Bs[kk][bc] = Wptr[(kbase + kk) * HE + col0 + bc];
        }
        __syncthreads();
#pragma unroll
        for (int kk = 0; kk < BK; ++kk) {
            float a[TM], bb[TN];
#pragma unroll
            for (int i = 0; i < TM; ++i) a[i] = As[kk][ty * TM + i];
#pragma unroll
            for (int j = 0; j < TN; ++j) bb[j] = Bs[kk][tx * TN + j];
#pragma unroll
            for (int i = 0; i < TM; ++i)
#pragma unroll
                for (int j = 0; j < TN; ++j) acc[i][j] += a[i] * bb[j];
        }
        __syncthreads();
    }
#pragma unroll
    for (int i = 0; i < TM; ++i) {
        int gb = row0 + ty * TM + i;
#pragma unroll
        for (int j = 0; j < TN; ++j) {
            int col = col0 + tx * TN + j;
            float v = acc[i][j] + (bias ? bias[col] : 0.f);
            Cptr[(size_t)gb * HE + col] = v;
        }
    }
}

// ---------------- decoder attention (row-wise fused) ----------------------
__global__ __launch_bounds__(256) void dec_attn_kernel(const float* __restrict__ yprev,
                                                       const float* __restrict__ a2w,
                                                       const float* __restrict__ a2b,
                                                       const float* __restrict__ fcw,
                                                       const float* __restrict__ fcb, int t) {
    int b = blockIdx.x;
    int h = threadIdx.x;
    float qh = g_q[b * HE + h];
    float w = a2w[h];
    const float* xp = g_xproj + (size_t)(b * T) * HE + h;
    float sloc[T];
#pragma unroll
    for (int tt = 0; tt < T; ++tt) sloc[tt] = ftanh(xp[tt * HE] + qh) * w;

    __shared__ float part[8][T];
    __shared__ float beta[T];
    int lane = h & 31, wid = h >> 5;
#pragma unroll
    for (int tt = 0; tt < T; ++tt) {
        float v = sloc[tt];
        for (int o = 16; o > 0; o >>= 1) v += __shfl_down_sync(0xFFFFFFFFu, v, o);
        if (!lane) part[wid][tt] = v;
    }
    __syncthreads();
    if (h == 0) {
        float sc[T];
        float mx = -1e30f;
#pragma unroll
        for (int tt = 0; tt < T; ++tt) {
            float s = a2b[0];
#pragma unroll
            for (int w8 = 0; w8 < 8; ++w8) s += part[w8][tt];
            sc[tt] = s;
            mx = fmaxf(mx, s);
        }
        float sum = 0.f;
#pragma unroll
        for (int tt = 0; tt < T; ++tt) { sc[tt] = __expf(sc[tt] - mx); sum += sc[tt]; }
        float inv = __fdividef(1.f, sum);
#pragma unroll
        for (int tt = 0; tt < T; ++tt) beta[tt] = sc[tt] * inv;
    }
    __syncthreads();
    const float* xe = g_Xenc + (size_t)(b * T) * HE + h;
    float ctx = 0.f;
#pragma unroll
    for (int tt = 0; tt < T; ++tt) ctx += beta[tt] * xe[tt * HE];
    g_ctx[b * HE + h] = ctx;
    float yv = ctx * fcw[h];
    for (int o = 16; o > 0; o >>= 1) yv += __shfl_down_sync(0xFFFFFFFFu, yv, o);
    __syncthreads();
    if (!lane) part[wid][0] = yv;
    __syncthreads();
    if (h == 0) {
        float s = 0.f;
#pragma unroll
        for (int w8 = 0; w8 < 8; ++w8) s += part[w8][0];
        g_yt[b] = s + yprev[b * T + t] * fcw[HE] + fcb[0];
    }
}

// ---------------- final output --------------------------------------------
__global__ void final_kernel(const float* __restrict__ ffw, const float* __restrict__ ffb,
                             float* __restrict__ out, int pin) {
    int gtid = blockIdx.x * blockDim.x + threadIdx.x;
    int warp = gtid >> 5;
    int lane = gtid & 31;
    if (warp >= B) return;
    const float* d = g_dc[pin] + warp * 512;
    const float* ctx = g_ctx + warp * HE;
    float s = 0.f;
    for (int h = lane; h < HE; h += 32) s += d[h] * ffw[h] + ctx[h] * ffw[HE + h];
    for (int o = 16; o > 0; o >>= 1) s += __shfl_down_sync(0xFFFFFFFFu, s, o);
    if (!lane) out[warp] = s + ffb[0];
}

// ---------------- launch ---------------------------------------------------
extern "C" void kernel_launch(void* const* d_in, const int* in_sizes, int n_in,
                              void* d_out, int out_size) {
    const float* X      = (const float*)d_in[0];
    const float* yprev  = (const float*)d_in[1];
    const float* e1w    = (const float*)d_in[2];
    const float* e1b    = (const float*)d_in[3];
    const float* e2w    = (const float*)d_in[4];
    const float* e2b    = (const float*)d_in[5];
    const float* l1_wih = (const float*)d_in[6];
    const float* l1_whh = (const float*)d_in[7];
    const float* l1_b   = (const float*)d_in[8];
    const float* l2_wih = (const float*)d_in[9];
    const float* l2_whh = (const float*)d_in[10];
    const float* l2_b   = (const float*)d_in[11];
    const float* da1w   = (const float*)d_in[12];
    const float* da1b   = (const float*)d_in[13];
    const float* da2w   = (const float*)d_in[14];
    const float* da2b   = (const float*)d_in[15];
    const float* dlwih  = (const float*)d_in[16];
    const float* dlwhh  = (const float*)d_in[17];
    const float* dlb    = (const float*)d_in[18];
    const float* fcw    = (const float*)d_in[19];
    const float* fcb    = (const float*)d_in[20];
    const float* ffw    = (const float*)d_in[21];
    const float* ffb    = (const float*)d_in[22];
    float* out = (float*)d_out;

    pack_kernel<<<512, 256>>>(l1_wih, l1_whh, l1_b, l2_wih, l2_whh, l2_b,
                              dlwih, dlwhh, dlb, da1w);
    init_kernel<<<512, 256>>>();
    attn_kernel<<<B, 128>>>(X, yprev, e1w, e1b, e2w, e2b);

    for (int t = 0; t < T; ++t)
        enc_step_kernel<<<dim3(B / BM, NG / BN, 2), 256>>>(X, t, t & 1, (t + 1) & 1);

    // xenc_proj over all (b, t)
    gemm256_kernel<<<dim3(B * T / BM, HE / BN), 256>>>(0, 0, da1b);

    for (int t = 0; t < T; ++t) {
        gemm256_kernel<<<dim3(B / BM, HE / BN), 256>>>(1, t & 1, nullptr);
        dec_attn_kernel<<<B, 256>>>(yprev, da2w, da2b, fcw, fcb, t);
        dec_lstm_kernel<<<dim3(B / BM, NG / BN), 256>>>(t & 1, (t + 1) & 1);
    }

    final_kernel<<<B * 32 / 256, 256>>>(ffw, ffb, out, T & 1);
}

// round 6
// speedup vs baseline: 2.1217x; 2.1217x over previous
#include <cuda_runtime.h>

#define B 8192
#define T 15
#define D 81
#define HE 256
#define NG 1024
#define KENC 337      // 81 (x) + 256 (h)
#define KENC_PAD 352  // 22 * 16
#define KDEC 257      // 1 (y_tilde) + 256 (d)
#define KDEC_PAD 272  // 17 * 16

#define BM 128
#define BN 64
#define BK 16
#define ASTRIDE 20    // 16 k + 4 pad  -> conflict-free a-frag LDS
#define BSTRIDE 72    // 64 cols + 8 pad (72 % 32 == 8) -> conflict-free b-frag LDS

// ---------------- scratch (static device memory; no allocations) ----------
__device__ float g_A1[B * D];
__device__ float g_A12[B * D];
__device__ float g_Wenc[2][KENC_PAD][NG];   // packed gate-interleaved cols (see pack)
__device__ float g_benc[2][NG];
__device__ float g_Wdec[KDEC_PAD][NG];
__device__ float g_bdec[NG];
__device__ float g_Wq[512][HE];             // [k][n]: k<256 -> W1d, else W1c
__device__ float g_Wxp[HE][HE];             // [k][n] = W1x[n][k]
__device__ float g_h1[2][B * HE];
__device__ float g_c1[2][B * HE];
__device__ float g_h2[2][B * HE];
__device__ float g_c2[2][B * HE];
__device__ float g_Xenc[B * T * HE];        // [b][t][h]
__device__ float g_xproj[B * T * HE];
__device__ float g_dc[2][B * 512];          // decoder state [d | c]
__device__ float g_q[B * HE];
__device__ float g_yt[B];
__device__ float g_ctx[B * HE];

// ---------------- math helpers -------------------------------------------
__device__ __forceinline__ float sigf(float x) {
    return __fdividef(1.f, 1.f + __expf(-x));
}
__device__ __forceinline__ float ftanh(float x) {
    float e = __expf(-2.f * fabsf(x));
    float r = __fdividef(1.f - e, 1.f + e);
    return copysignf(r, x);
}
__device__ __forceinline__ void mma_tf32(float* c, const unsigned* a, const unsigned* b) {
    asm volatile(
        "mma.sync.aligned.m16n8k8.row.col.f32.tf32.tf32.f32 "
        "{%0,%1,%2,%3}, {%4,%5,%6,%7}, {%8,%9}, {%0,%1,%2,%3};\n"
        : "+f"(c[0]), "+f"(c[1]), "+f"(c[2]), "+f"(c[3])
        : "r"(a[0]), "r"(a[1]), "r"(a[2]), "r"(a[3]), "r"(b[0]), "r"(b[1]));
}

// Packed column mapping for LSTM weights:
// col c in [0,1024): g32 = c>>5, p = c&31
//   unit u = g32*8 + ((p&15)>>1),  gate = ((p&16)?2:0) + (p&1)   (i,f,g,o = 0..3)
//   original row n = gate*256 + u
__device__ __forceinline__ int lstm_src_n(int c) {
    int g32 = c >> 5, p = c & 31;
    int u = (g32 << 3) + ((p & 15) >> 1);
    int gate = ((p & 16) ? 2 : 0) + (p & 1);
    return gate * HE + u;
}

// ---------------- weight packing ------------------------------------------
__global__ void pack_kernel(const float* __restrict__ l1_wih, const float* __restrict__ l1_whh,
                            const float* __restrict__ l1_b,
                            const float* __restrict__ l2_wih, const float* __restrict__ l2_whh,
                            const float* __restrict__ l2_b,
                            const float* __restrict__ dl_wih, const float* __restrict__ dl_whh,
                            const float* __restrict__ dl_b,
                            const float* __restrict__ da1w) {
    int stride = gridDim.x * blockDim.x;
    int idx0 = blockIdx.x * blockDim.x + threadIdx.x;
    for (int i = idx0; i < KENC_PAD * NG; i += stride) {
        int k = i >> 10, col = i & 1023;
        int n = lstm_src_n(col);
        float v1 = 0.f, v2 = 0.f;
        if (k < D)         { v1 = l1_wih[n * D + k];        v2 = l2_wih[n * D + k]; }
        else if (k < KENC) { v1 = l1_whh[n * HE + (k - D)]; v2 = l2_whh[n * HE + (k - D)]; }
        g_Wenc[0][k][col] = v1;
        g_Wenc[1][k][col] = v2;
    }
    for (int i = idx0; i < KDEC_PAD * NG; i += stride) {
        int k = i >> 10, col = i & 1023;
        int n = lstm_src_n(col);
        float v = 0.f;
        if (k == 0)        v = dl_wih[n];
        else if (k < KDEC) v = dl_whh[n * HE + (k - 1)];
        g_Wdec[k][col] = v;
    }
    for (int i = idx0; i < 512 * HE; i += stride) {
        int k = i >> 8, n = i & 255;
        g_Wq[k][n] = (k < HE) ? da1w[n * 768 + k] : da1w[n * 768 + 256 + (k - HE)];
    }
    for (int i = idx0; i < HE * HE; i += stride) {
        int k = i >> 8, n = i & 255;
        g_Wxp[k][n] = da1w[n * 768 + 512 + k];
    }
    for (int i = idx0; i < NG; i += stride) {
        int n = lstm_src_n(i);
        g_benc[0][i] = l1_b[n];
        g_benc[1][i] = l2_b[n];
        g_bdec[i]    = dl_b[n];
    }
}

__global__ void init_kernel() {
    int stride = gridDim.x * blockDim.x;
    int i0 = blockIdx.x * blockDim.x + threadIdx.x;
    for (int j = i0; j < B * HE; j += stride) {
        g_h1[0][j] = 0.f; g_c1[0][j] = 0.f;
        g_h2[0][j] = 0.f; g_c2[0][j] = 0.f;
    }
    for (int j = i0; j < B * 512; j += stride) g_dc[0][j] = 0.f;
}

// ---------------- input attention (a1, a1*a2) — state-independent ---------
__global__ void attn_kernel(const float* __restrict__ X, const float* __restrict__ yprev,
                            const float* __restrict__ e1w, const float* __restrict__ e1b,
                            const float* __restrict__ e2w, const float* __restrict__ e2b) {
    int b = blockIdx.x;
    int j = threadIdx.x;
    float v1 = -1e30f, v2 = -1e30f;
    if (j < D) {
        const float* xb = X + (size_t)b * T * D + j;
        float s1 = 0.f, s2 = 0.f;
#pragma unroll
        for (int t = 0; t < T; ++t) {
            float x = xb[t * D];
            s1 += x * e1w[2 * HE + t];
            s2 += x * e2w[2 * HE + t];
        }
        float yw = 0.f;
#pragma unroll
        for (int t = 0; t < T; ++t) yw += yprev[b * T + t] * e2w[2 * HE + T + t];
        v1 = s1 + e1b[0];
        v2 = s2 + yw + e2b[0];
    }
    __shared__ float red1[128], red2[128];
    red1[j] = v1; red2[j] = v2;
    __syncthreads();
    for (int o = 64; o > 0; o >>= 1) {
        if (j < o) {
            red1[j] = fmaxf(red1[j], red1[j + o]);
            red2[j] = fmaxf(red2[j], red2[j + o]);
        }
        __syncthreads();
    }
    float m1 = red1[0], m2 = red2[0];
    __syncthreads();
    float e1v = (j < D) ? __expf(v1 - m1) : 0.f;
    float e2v = (j < D) ? __expf(v2 - m2) : 0.f;
    red1[j] = e1v; red2[j] = e2v;
    __syncthreads();
    for (int o = 64; o > 0; o >>= 1) {
        if (j < o) { red1[j] += red1[j + o]; red2[j] += red2[j + o]; }
        __syncthreads();
    }
    if (j < D) {
        float a1 = __fdividef(e1v, red1[0]);
        float a2 = __fdividef(e2v, red2[0]);
        g_A1[b * D + j]  = a1;
        g_A12[b * D + j] = a1 * a2;
    }
}

// ============= tf32 tensor-core GEMM + fused LSTM epilogue =================
// MODE 0: encoder step (grid.z selects layer); MODE 1: decoder LSTM
template <int MODE>
__global__ __launch_bounds__(256) void lstm_mma_kernel(const float* __restrict__ X, int t,
                                                       int pin, int pout) {
    const float* scale = nullptr;
    const float* hin = nullptr;
    const float* cin = nullptr;
    float* hout = nullptr;
    float* cout = nullptr;
    const float* Wg;
    const float* bias;
    const float* dcin = nullptr;
    float* dcout = nullptr;
    int L = 0;
    int NC;
    if (MODE == 0) {
        L = blockIdx.z;
        scale = L ? g_A12 : g_A1;
        hin = L ? g_h2[pin] : g_h1[pin];
        cin = L ? g_c2[pin] : g_c1[pin];
        hout = L ? g_h2[pout] : g_h1[pout];
        cout = L ? g_c2[pout] : g_c1[pout];
        Wg = &g_Wenc[L][0][0];
        bias = g_benc[L];
        NC = KENC_PAD / BK;
    } else {
        dcin = g_dc[pin];
        dcout = g_dc[pout];
        Wg = &g_Wdec[0][0];
        bias = g_bdec;
        NC = KDEC_PAD / BK;
    }

    __shared__ float As[2][BM * ASTRIDE];
    __shared__ float Bs[2][BK * BSTRIDE];

    int tid = threadIdx.x;
    int lane = tid & 31;
    int wid = tid >> 5;
    int wm = wid & 3, wn = wid >> 2;      // 4 row-warps x 2 col-warps
    int lq = lane & 3, lr = lane >> 2;
    int row0 = blockIdx.x * BM;
    int col0 = blockIdx.y * BN;

    // A loader indices: 8 scalars per thread per chunk
    int ak = tid & 15;        // k within chunk
    int ar0 = tid >> 4;       // row base (stride 16)
    // B loader: one float4 per thread per chunk
    int bc4 = (tid & 15) * 4;
    int bk = tid >> 4;

    float acc[2][4][4] = {};
    float avp[8];
    float4 bvp;

    // ---- load chunk into regs ----
    auto loadChunk = [&](int kc) {
        int k = kc * BK + ak;
#pragma unroll
        for (int i = 0; i < 8; ++i) {
            int gb = row0 + ar0 + 16 * i;
            float v;
            if (MODE == 0) {
                if (k < D)         v = scale[gb * D + k] * X[(size_t)gb * (T * D) + t * D + k];
                else if (k < KENC) v = hin[gb * HE + (k - D)];
                else               v = 0.f;
            } else {
                if (k == 0)        v = g_yt[gb];
                else if (k < KDEC) v = dcin[gb * 512 + (k - 1)];
                else               v = 0.f;
            }
            avp[i] = v;
        }
        bvp = *(const float4*)&Wg[(size_t)(kc * BK + bk) * NG + col0 + bc4];
    };
    auto storeChunk = [&](int buf) {
#pragma unroll
        for (int i = 0; i < 8; ++i)
            As[buf][(ar0 + 16 * i) * ASTRIDE + ak] = avp[i];
        *(float4*)&Bs[buf][bk * BSTRIDE + bc4] = bvp;
    };
    auto compute = [&](int buf) {
        const float* as = As[buf];
        const float* bs = Bs[buf];
#pragma unroll
        for (int kf = 0; kf < 2; ++kf) {
            unsigned a[2][4], b[4][2];
#pragma unroll
            for (int mi = 0; mi < 2; ++mi) {
                int r = wm * 32 + mi * 16 + lr;
                a[mi][0] = __float_as_uint(as[r * ASTRIDE + kf * 8 + lq]);
                a[mi][1] = __float_as_uint(as[(r + 8) * ASTRIDE + kf * 8 + lq]);
                a[mi][2] = __float_as_uint(as[r * ASTRIDE + kf * 8 + lq + 4]);
                a[mi][3] = __float_as_uint(as[(r + 8) * ASTRIDE + kf * 8 + lq + 4]);
            }
#pragma unroll
            for (int ni = 0; ni < 4; ++ni) {
                int c = wn * 32 + ni * 8 + lr;
                b[ni][0] = __float_as_uint(bs[(kf * 8 + lq) * BSTRIDE + c]);
                b[ni][1] = __float_as_uint(bs[(kf * 8 + lq + 4) * BSTRIDE + c]);
            }
#pragma unroll
            for (int mi = 0; mi < 2; ++mi)
#pragma unroll
                for (int ni = 0; ni < 4; ++ni) mma_tf32(acc[mi][ni], a[mi], b[ni]);
        }
    };

    loadChunk(0);
    storeChunk(0);
    __syncthreads();
#pragma unroll 1
    for (int kc = 0; kc < NC; ++kc) {
        int cur = kc & 1;
        if (kc + 1 < NC) loadChunk(kc + 1);
        compute(cur);
        if (kc + 1 < NC) storeChunk(cur ^ 1);
        __syncthreads();
    }

    // ---- fused LSTM epilogue on gate-interleaved columns ----
    int cbase = col0 + wn * 32;
#pragma unroll
    for (int upair = 0; upair < 2; ++upair) {
        int unit = (cbase >> 2) + upair * 4 + lq;
        float bI = bias[cbase + upair * 8 + 2 * lq];
        float bF = bias[cbase + upair * 8 + 2 * lq + 1];
        float bG = bias[cbase + 16 + upair * 8 + 2 * lq];
        float bO = bias[cbase + 16 + upair * 8 + 2 * lq + 1];
#pragma unroll
        for (int mi = 0; mi < 2; ++mi) {
#pragma unroll
            for (int half = 0; half < 2; ++half) {
                int gb = row0 + wm * 32 + mi * 16 + half * 8 + lr;
                float gi = acc[mi][upair][half * 2 + 0] + bI;
                float gf = acc[mi][upair][half * 2 + 1] + bF;
                float gg = acc[mi][2 + upair][half * 2 + 0] + bG;
                float go = acc[mi][2 + upair][half * 2 + 1] + bO;
                float cold = (MODE == 0) ? cin[gb * HE + unit]
                                         : dcin[gb * 512 + 256 + unit];
                float c2 = sigf(gf) * cold + sigf(gi) * ftanh(gg);
                float h2 = sigf(go) * ftanh(c2);
                if (MODE == 0) {
                    hout[gb * HE + unit] = h2;
                    cout[gb * HE + unit] = c2;
                    if (L) g_Xenc[((size_t)gb * T + t) * HE + unit] = h2;
                } else {
                    dcout[gb * 512 + unit] = h2;
                    dcout[gb * 512 + 256 + unit] = c2;
                }
            }
        }
    }
}

// ---------------- tf32 plain GEMM, N=256 (xenc_proj and q) ----------------
// mode 0: xproj = Xenc @ Wxp + da1b   (M = B*T, K = 256)
// mode 1: q     = [d|c] @ Wq          (M = B,   K = 512)
__global__ __launch_bounds__(256) void gemm256_mma_kernel(int mode, int pin,
                                                          const float* __restrict__ bias) {
    const float* Aptr;
    const float* Wptr;
    float* Cptr;
    int lda, NC;
    if (mode == 0) { Aptr = g_Xenc;    Wptr = &g_Wxp[0][0]; Cptr = g_xproj; lda = 256; NC = 16; }
    else           { Aptr = g_dc[pin]; Wptr = &g_Wq[0][0];  Cptr = g_q;     lda = 512; NC = 32; }

    __shared__ float As[2][BM * ASTRIDE];
    __shared__ float Bs[2][BK * BSTRIDE];

    int tid = threadIdx.x;
    int lane = tid & 31;
    int wid = tid >> 5;
    int wm = wid & 3, wn = wid >> 2;
    int lq = lane & 3, lr = lane >> 2;
    int row0 = blockIdx.x * BM;
    int col0 = blockIdx.y * BN;

    int ak = tid & 15;
    int ar0 = tid >> 4;
    int bc4 = (tid & 15) * 4;
    int bk = tid >> 4;

    float acc[2][4][4] = {};
    float avp[8];
    float4 bvp;

    auto loadChunk = [&](int kc) {
        int k = kc * BK + ak;
#pragma unroll
        for (int i = 0; i < 8; ++i)
            avp[i] = Aptr[(size_t)(row0 + ar0 + 16 * i) * lda + k];
        bvp = *(const float4*)&Wptr[(kc * BK + bk) * HE + col0 + bc4];
    };
    auto storeChunk = [&](int buf) {
#pragma unroll
        for (int i = 0; i < 8; ++i)
            As[buf][(ar0 + 16 * i) * ASTRIDE + ak] = avp[i];
        *(float4*)&Bs[buf][bk * BSTRIDE + bc4] = bvp;
    };
    auto compute = [&](int buf) {
        const float* as = As[buf];
        const float* bs = Bs[buf];
#pragma unroll
        for (int kf = 0; kf < 2; ++kf) {
            unsigned a[2][4], b[4][2];
#pragma unroll
            for (int mi = 0; mi < 2; ++mi) {
                int r = wm * 32 + mi * 16 + lr;
                a[mi][0] = __float_as_uint(as[r * ASTRIDE + kf * 8 + lq]);
                a[mi][1] = __float_as_uint(as[(r + 8) * ASTRIDE + kf * 8 + lq]);
                a[mi][2] = __float_as_uint(as[r * ASTRIDE + kf * 8 + lq + 4]);
                a[mi][3] = __float_as_uint(as[(r + 8) * ASTRIDE + kf * 8 + lq + 4]);
            }
#pragma unroll
            for (int ni = 0; ni < 4; ++ni) {
                int c = wn * 32 + ni * 8 + lr;
                b[ni][0] = __float_as_uint(bs[(kf * 8 + lq) * BSTRIDE + c]);
                b[ni][1] = __float_as_uint(bs[(kf * 8 + lq + 4) * BSTRIDE + c]);
            }
#pragma unroll
            for (int mi = 0; mi < 2; ++mi)
#pragma unroll
                for (int ni = 0; ni < 4; ++ni) mma_tf32(acc[mi][ni], a[mi], b[ni]);
        }
    };

    loadChunk(0);
    storeChunk(0);
    __syncthreads();
#pragma unroll 1
    for (int kc = 0; kc < NC; ++kc) {
        int cur = kc & 1;
        if (kc + 1 < NC) loadChunk(kc + 1);
        compute(cur);
        if (kc + 1 < NC) storeChunk(cur ^ 1);
        __syncthreads();
    }

#pragma unroll
    for (int mi = 0; mi < 2; ++mi) {
#pragma unroll
        for (int half = 0; half < 2; ++half) {
            int gb = row0 + wm * 32 + mi * 16 + half * 8 + lr;
#pragma unroll
            for (int ni = 0; ni < 4; ++ni) {
                int col = col0 + wn * 32 + ni * 8 + 2 * lq;
                float v0 = acc[mi][ni][half * 2 + 0] + (bias ? bias[col] : 0.f);
                float v1 = acc[mi][ni][half * 2 + 1] + (bias ? bias[col + 1] : 0.f);
                *(float2*)&Cptr[(size_t)gb * HE + col] = make_float2(v0, v1);
            }
        }
    }
}

// ---------------- decoder attention (row-wise fused) ----------------------
__global__ __launch_bounds__(256) void dec_attn_kernel(const float* __restrict__ yprev,
                                                       const float* __restrict__ a2w,
                                                       const float* __restrict__ a2b,
                                                       const float* __restrict__ fcw,
                                                       const float* __restrict__ fcb, int t) {
    int b = blockIdx.x;
    int h = threadIdx.x;
    float qh = g_q[b * HE + h];
    float w = a2w[h];
    const float* xp = g_xproj + (size_t)(b * T) * HE + h;
    float sloc[T];
#pragma unroll
    for (int tt = 0; tt < T; ++tt) sloc[tt] = ftanh(xp[tt * HE] + qh) * w;

    __shared__ float part[8][T];
    __shared__ float beta[T];
    int lane = h & 31, wid = h >> 5;
#pragma unroll
    for (int tt = 0; tt < T; ++tt) {
        float v = sloc[tt];
        for (int o = 16; o > 0; o >>= 1) v += __shfl_down_sync(0xFFFFFFFFu, v, o);
        if (!lane) part[wid][tt] = v;
    }
    __syncthreads();
    if (h == 0) {
        float sc[T];
        float mx = -1e30f;
#pragma unroll
        for (int tt = 0; tt < T; ++tt) {
            float s = a2b[0];
#pragma unroll
            for (int w8 = 0; w8 < 8; ++w8) s += part[w8][tt];
            sc[tt] = s;
            mx = fmaxf(mx, s);
        }
        float sum = 0.f;
#pragma unroll
        for (int tt = 0; tt < T; ++tt) { sc[tt] = __expf(sc[tt] - mx); sum += sc[tt]; }
        float inv = __fdividef(1.f, sum);
#pragma unroll
        for (int tt = 0; tt < T; ++tt) beta[tt] = sc[tt] * inv;
    }
    __syncthreads();
    const float* xe = g_Xenc + (size_t)(b * T) * HE + h;
    float ctx = 0.f;
#pragma unroll
    for (int tt = 0; tt < T; ++tt) ctx += beta[tt] * xe[tt * HE];
    g_ctx[b * HE + h] = ctx;
    float yv = ctx * fcw[h];
    for (int o = 16; o > 0; o >>= 1) yv += __shfl_down_sync(0xFFFFFFFFu, yv, o);
    __syncthreads();
    if (!lane) part[wid][0] = yv;
    __syncthreads();
    if (h == 0) {
        float s = 0.f;
#pragma unroll
        for (int w8 = 0; w8 < 8; ++w8) s += part[w8][0];
        g_yt[b] = s + yprev[b * T + t] * fcw[HE] + fcb[0];
    }
}

// ---------------- final output --------------------------------------------
__global__ void final_kernel(const float* __restrict__ ffw, const float* __restrict__ ffb,
                             float* __restrict__ out, int pin) {
    int gtid = blockIdx.x * blockDim.x + threadIdx.x;
    int warp = gtid >> 5;
    int lane = gtid & 31;
    if (warp >= B) return;
    const float* d = g_dc[pin] + warp * 512;
    const float* ctx = g_ctx + warp * HE;
    float s = 0.f;
    for (int h = lane; h < HE; h += 32) s += d[h] * ffw[h] + ctx[h] * ffw[HE + h];
    for (int o = 16; o > 0; o >>= 1) s += __shfl_down_sync(0xFFFFFFFFu, s, o);
    if (!lane) out[warp] = s + ffb[0];
}

// ---------------- launch ---------------------------------------------------
extern "C" void kernel_launch(void* const* d_in, const int* in_sizes, int n_in,
                              void* d_out, int out_size) {
    const float* X      = (const float*)d_in[0];
    const float* yprev  = (const float*)d_in[1];
    const float* e1w    = (const float*)d_in[2];
    const float* e1b    = (const float*)d_in[3];
    const float* e2w    = (const float*)d_in[4];
    const float* e2b    = (const float*)d_in[5];
    const float* l1_wih = (const float*)d_in[6];
    const float* l1_whh = (const float*)d_in[7];
    const float* l1_b   = (const float*)d_in[8];
    const float* l2_wih = (const float*)d_in[9];
    const float* l2_whh = (const float*)d_in[10];
    const float* l2_b   = (const float*)d_in[11];
    const float* da1w   = (const float*)d_in[12];
    const float* da1b   = (const float*)d_in[13];
    const float* da2w   = (const float*)d_in[14];
    const float* da2b   = (const float*)d_in[15];
    const float* dlwih  = (const float*)d_in[16];
    const float* dlwhh  = (const float*)d_in[17];
    const float* dlb    = (const float*)d_in[18];
    const float* fcw    = (const float*)d_in[19];
    const float* fcb    = (const float*)d_in[20];
    const float* ffw    = (const float*)d_in[21];
    const float* ffb    = (const float*)d_in[22];
    float* out = (float*)d_out;

    pack_kernel<<<512, 256>>>(l1_wih, l1_whh, l1_b, l2_wih, l2_whh, l2_b,
                              dlwih, dlwhh, dlb, da1w);
    init_kernel<<<512, 256>>>();
    attn_kernel<<<B, 128>>>(X, yprev, e1w, e1b, e2w, e2b);

    for (int t = 0; t < T; ++t)
        lstm_mma_kernel<0><<<dim3(B / BM, NG / BN, 2), 256>>>(X, t, t & 1, (t + 1) & 1);

    // xenc_proj over all (b, t)
    gemm256_mma_kernel<<<dim3(B * T / BM, HE / BN), 256>>>(0, 0, da1b);

    for (int t = 0; t < T; ++t) {
        gemm256_mma_kernel<<<dim3(B / BM, HE / BN), 256>>>(1, t & 1, nullptr);
        dec_attn_kernel<<<B, 256>>>(yprev, da2w, da2b, fcw, fcb, t);
        lstm_mma_kernel<1><<<dim3(B / BM, NG / BN), 256>>>(nullptr, 0, t & 1, (t + 1) & 1);
    }

    final_kernel<<<B * 32 / 256, 256>>>(ffw, ffb, out, T & 1);
}

// round 9
// speedup vs baseline: 2.1711x; 1.0233x over previous
#include <cuda_runtime.h>

#define B 8192
#define T 15
#define D 81
#define HE 256
#define NG 1024
#define KENC 337      // 81 (x) + 256 (h)
#define KENC_PAD 352  // 22 * 16
#define KDEC 257      // 1 (y_tilde) + 256 (d)
#define KDEC_PAD 272  // 17 * 16

#define BM 128
#define BN 64
#define BK 16
#define AKF 1032      // per-kf A block: 8 mt * 32 lane * 4 slot + 8 pad
#define ABUF (2 * AKF)
#define BBUF 1024     // 2 kf * 8 nt * 32 lane * 2 slot

// ---------------- scratch (static device memory; no allocations) ----------
__device__ float g_A1[B * D];
__device__ float g_A12[B * D];
__device__ float g_Wenc[2][KENC_PAD * NG];  // fragment-packed (see frag_idx)
__device__ float g_benc[2][NG];
__device__ float g_Wdec[KDEC_PAD * NG];     // fragment-packed
__device__ float g_bdec[NG];
__device__ float g_Wq[512 * HE];            // fragment-packed; k<256 -> W1d, else W1c
__device__ float g_Wxp[HE * HE];            // fragment-packed; [k][n] = W1x[n][k]
__device__ float g_h1[2][B * HE];
__device__ float g_c1[2][B * HE];
__device__ float g_h2[2][B * HE];
__device__ float g_c2[2][B * HE];
__device__ float g_Xenc[B * T * HE];        // [b][t][h]
__device__ float g_xproj[B * T * HE];
__device__ float g_dc[2][B * 512];          // decoder state [d | c]
__device__ float g_q[B * HE];
__device__ float g_yt[B];
__device__ float g_ctx[B * HE];

// ---------------- math helpers -------------------------------------------
__device__ __forceinline__ float sigf(float x) {
    return __fdividef(1.f, 1.f + __expf(-x));
}
__device__ __forceinline__ float ftanh(float x) {
    float e = __expf(-2.f * fabsf(x));
    float r = __fdividef(1.f - e, 1.f + e);
    return copysignf(r, x);
}
__device__ __forceinline__ void mma_tf32(float* c, const unsigned* a, const unsigned* b) {
    asm volatile(
        "mma.sync.aligned.m16n8k8.row.col.f32.tf32.tf32.f32 "
        "{%0,%1,%2,%3}, {%4,%5,%6,%7}, {%8,%9}, {%0,%1,%2,%3};\n"
        : "+f"(c[0]), "+f"(c[1]), "+f"(c[2]), "+f"(c[3])
        : "r"(a[0]), "r"(a[1]), "r"(a[2]), "r"(a[3]), "r"(b[0]), "r"(b[1]));
}

// Fragment-packed B-weight index.
// Element (k, c) of a [K][NCOLS] col-major-N weight (NCOLS = ncg*64):
//   kc = k>>4 (16-k chunk), kf = (k>>3)&1, kq = k&7
//   cg = c>>6, nt = (c&63)>>3, lane = (c&7)*4 + (kq&3), slot = (kq>>2)&1
__device__ __forceinline__ size_t frag_idx(int k, int c, int ncg) {
    int kc = k >> 4, kf = (k >> 3) & 1, kq = k & 7;
    int cg = c >> 6, nt = (c & 63) >> 3;
    int lane = ((c & 7) << 2) + (kq & 3);
    int slot = (kq >> 2) & 1;
    return ((((size_t)(kc * ncg + cg) * 2 + kf) * 8 + nt) * 64) + lane * 2 + slot;
}

// Packed column mapping for LSTM weights:
// col c in [0,1024): g32 = c>>5, p = c&31
//   unit u = g32*8 + ((p&15)>>1),  gate = ((p&16)?2:0) + (p&1)   (i,f,g,o = 0..3)
//   original row n = gate*256 + u
__device__ __forceinline__ int lstm_src_n(int c) {
    int g32 = c >> 5, p = c & 31;
    int u = (g32 << 3) + ((p & 15) >> 1);
    int gate = ((p & 16) ? 2 : 0) + (p & 1);
    return gate * HE + u;
}

// ---------------- weight packing ------------------------------------------
__global__ void pack_kernel(const float* __restrict__ l1_wih, const float* __restrict__ l1_whh,
                            const float* __restrict__ l1_b,
                            const float* __restrict__ l2_wih, const float* __restrict__ l2_whh,
                            const float* __restrict__ l2_b,
                            const float* __restrict__ dl_wih, const float* __restrict__ dl_whh,
                            const float* __restrict__ dl_b,
                            const float* __restrict__ da1w) {
    int stride = gridDim.x * blockDim.x;
    int idx0 = blockIdx.x * blockDim.x + threadIdx.x;
    for (int i = idx0; i < KENC_PAD * NG; i += stride) {
        int k = i >> 10, col = i & 1023;
        int n = lstm_src_n(col);
        float v1 = 0.f, v2 = 0.f;
        if (k < D)         { v1 = l1_wih[n * D + k];        v2 = l2_wih[n * D + k]; }
        else if (k < KENC) { v1 = l1_whh[n * HE + (k - D)]; v2 = l2_whh[n * HE + (k - D)]; }
        size_t fi = frag_idx(k, col, 16);
        g_Wenc[0][fi] = v1;
        g_Wenc[1][fi] = v2;
    }
    for (int i = idx0; i < KDEC_PAD * NG; i += stride) {
        int k = i >> 10, col = i & 1023;
        int n = lstm_src_n(col);
        float v = 0.f;
        if (k == 0)        v = dl_wih[n];
        else if (k < KDEC) v = dl_whh[n * HE + (k - 1)];
        g_Wdec[frag_idx(k, col, 16)] = v;
    }
    for (int i = idx0; i < 512 * HE; i += stride) {
        int k = i >> 8, n = i & 255;
        float v = (k < HE) ? da1w[n * 768 + k] : da1w[n * 768 + 256 + (k - HE)];
        g_Wq[frag_idx(k, n, 4)] = v;
    }
    for (int i = idx0; i < HE * HE; i += stride) {
        int k = i >> 8, n = i & 255;
        g_Wxp[frag_idx(k, n, 4)] = da1w[n * 768 + 512 + k];
    }
    for (int i = idx0; i < NG; i += stride) {
        int n = lstm_src_n(i);
        g_benc[0][i] = l1_b[n];
        g_benc[1][i] = l2_b[n];
        g_bdec[i]    = dl_b[n];
    }
}

__global__ void init_kernel() {
    int stride = gridDim.x * blockDim.x;
    int i0 = blockIdx.x * blockDim.x + threadIdx.x;
    for (int j = i0; j < B * HE; j += stride) {
        g_h1[0][j] = 0.f; g_c1[0][j] = 0.f;
        g_h2[0][j] = 0.f; g_c2[0][j] = 0.f;
    }
    for (int j = i0; j < B * 512; j += stride) g_dc[0][j] = 0.f;
}

// ---------------- input attention (a1, a1*a2) — state-independent ---------
__global__ void attn_kernel(const float* __restrict__ X, const float* __restrict__ yprev,
                            const float* __restrict__ e1w, const float* __restrict__ e1b,
                            const float* __restrict__ e2w, const float* __restrict__ e2b) {
    int b = blockIdx.x;
    int j = threadIdx.x;
    float v1 = -1e30f, v2 = -1e30f;
    if (j < D) {
        const float* xb = X + (size_t)b * T * D + j;
        float s1 = 0.f, s2 = 0.f;
#pragma unroll
        for (int t = 0; t < T; ++t) {
            float x = xb[t * D];
            s1 += x * e1w[2 * HE + t];
            s2 += x * e2w[2 * HE + t];
        }
        float yw = 0.f;
#pragma unroll
        for (int t = 0; t < T; ++t) yw += yprev[b * T + t] * e2w[2 * HE + T + t];
        v1 = s1 + e1b[0];
        v2 = s2 + yw + e2b[0];
    }
    __shared__ float red1[128], red2[128];
    red1[j] = v1; red2[j] = v2;
    __syncthreads();
    for (int o = 64; o > 0; o >>= 1) {
        if (j < o) {
            red1[j] = fmaxf(red1[j], red1[j + o]);
            red2[j] = fmaxf(red2[j], red2[j + o]);
        }
        __syncthreads();
    }
    float m1 = red1[0], m2 = red2[0];
    __syncthreads();
    float e1v = (j < D) ? __expf(v1 - m1) : 0.f;
    float e2v = (j < D) ? __expf(v2 - m2) : 0.f;
    red1[j] = e1v; red2[j] = e2v;
    __syncthreads();
    for (int o = 64; o > 0; o >>= 1) {
        if (j < o) { red1[j] += red1[j + o]; red2[j] += red2[j + o]; }
        __syncthreads();
    }
    if (j < D) {
        float a1 = __fdividef(e1v, red1[0]);
        float a2 = __fdividef(e2v, red2[0]);
        g_A1[b * D + j]  = a1;
        g_A12[b * D + j] = a1 * a2;
    }
}

// ============= tf32 tensor-core GEMM + fused LSTM epilogue =================
// MODE 0: encoder step (grid.z selects layer); MODE 1: decoder LSTM
template <int MODE>
__global__ __launch_bounds__(256) void lstm_mma_kernel(const float* __restrict__ X, int t,
                                                       int pin, int pout) {
    const float* scale = nullptr;
    const float* hin = nullptr;
    const float* cin = nullptr;
    float* hout = nullptr;
    float* cout = nullptr;
    const float* Wg;
    const float* bias;
    const float* dcin = nullptr;
    float* dcout = nullptr;
    int L = 0;
    int NC;
    if (MODE == 0) {
        L = blockIdx.z;
        scale = L ? g_A12 : g_A1;
        hin = L ? g_h2[pin] : g_h1[pin];
        cin = L ? g_c2[pin] : g_c1[pin];
        hout = L ? g_h2[pout] : g_h1[pout];
        cout = L ? g_c2[pout] : g_c1[pout];
        Wg = g_Wenc[L];
        bias = g_benc[L];
        NC = KENC_PAD / BK;
    } else {
        dcin = g_dc[pin];
        dcout = g_dc[pout];
        Wg = g_Wdec;
        bias = g_bdec;
        NC = KDEC_PAD / BK;
    }

    __shared__ __align__(16) float As[2][ABUF];
    __shared__ __align__(16) float Bs[2][BBUF];

    int tid = threadIdx.x;
    int lane = tid & 31;
    int wid = tid >> 5;
    int wm = wid & 3, wn = wid >> 2;      // 4 row-warps x 2 col-warps
    int lq = lane & 3, lr = lane >> 2;
    int row0 = blockIdx.x * BM;
    int col0 = blockIdx.y * BN;
    int cg = col0 >> 6;

    // A loader: thread owns fixed k (ak) and fixed rl (ar0), 8 row-tiles
    int ak = tid & 15;
    int ar0 = tid >> 4;
    int akf = ak >> 3, akq = ak & 7;
    int alane = ((ar0 & 7) << 2) + (akq & 3);
    int aslot = ((akq >> 2) & 1) * 2 + ((ar0 >> 3) & 1);
    int abase = akf * AKF + alane * 4 + aslot;

    float acc[2][4][4] = {};
    float avp[8];
    float4 bvp;

    auto loadChunk = [&](int kc) {
        int k = kc * BK + ak;
#pragma unroll
        for (int i = 0; i < 8; ++i) {
            int gb = row0 + ar0 + 16 * i;
            float v;
            if (MODE == 0) {
                if (k < D)         v = scale[gb * D + k] * X[(size_t)gb * (T * D) + t * D + k];
                else if (k < KENC) v = hin[gb * HE + (k - D)];
                else               v = 0.f;
            } else {
                if (k == 0)        v = g_yt[gb];
                else if (k < KDEC) v = dcin[gb * 512 + (k - 1)];
                else               v = 0.f;
            }
            avp[i] = v;
        }
        bvp = *(const float4*)&Wg[((size_t)(kc * 16 + cg) << 10) + (tid << 2)];
    };
    auto storeChunk = [&](int buf) {
#pragma unroll
        for (int i = 0; i < 8; ++i)
            As[buf][abase + i * 128] = avp[i];
        *(float4*)&Bs[buf][tid << 2] = bvp;
    };
    auto compute = [&](int buf) {
        const float* as = As[buf];
        const float* bs = Bs[buf];
#pragma unroll
        for (int kf = 0; kf < 2; ++kf) {
            float4 afr[2];
            float2 bfr[4];
#pragma unroll
            for (int mi = 0; mi < 2; ++mi)
                afr[mi] = *(const float4*)&as[kf * AKF + (wm * 2 + mi) * 128 + lane * 4];
#pragma unroll
            for (int ni = 0; ni < 4; ++ni)
                bfr[ni] = *(const float2*)&bs[kf * 512 + (wn * 4 + ni) * 64 + lane * 2];
#pragma unroll
            for (int mi = 0; mi < 2; ++mi)
#pragma unroll
                for (int ni = 0; ni < 4; ++ni)
                    mma_tf32(acc[mi][ni], (const unsigned*)&afr[mi], (const unsigned*)&bfr[ni]);
        }
    };

    loadChunk(0);
    storeChunk(0);
    __syncthreads();
#pragma unroll 1
    for (int kc = 0; kc < NC; ++kc) {
        int cur = kc & 1;
        if (kc + 1 < NC) loadChunk(kc + 1);
        compute(cur);
        if (kc + 1 < NC) storeChunk(cur ^ 1);
        __syncthreads();
    }

    // ---- fused LSTM epilogue on gate-interleaved columns ----
    int cbase = col0 + wn * 32;
#pragma unroll
    for (int upair = 0; upair < 2; ++upair) {
        int unit = (cbase >> 2) + upair * 4 + lq;
        float bI = bias[cbase + upair * 8 + 2 * lq];
        float bF = bias[cbase + upair * 8 + 2 * lq + 1];
        float bG = bias[cbase + 16 + upair * 8 + 2 * lq];
        float bO = bias[cbase + 16 + upair * 8 + 2 * lq + 1];
#pragma unroll
        for (int mi = 0; mi < 2; ++mi) {
#pragma unroll
            for (int half = 0; half < 2; ++half) {
                int gb = row0 + wm * 32 + mi * 16 + half * 8 + lr;
                float gi = acc[mi][upair][half * 2 + 0] + bI;
                float gf = acc[mi][upair][half * 2 + 1] + bF;
                float gg = acc[mi][2 + upair][half * 2 + 0] + bG;
                float go = acc[mi][2 + upair][half * 2 + 1] + bO;
                float cold = (MODE == 0) ? cin[gb * HE + unit]
                                         : dcin[gb * 512 + 256 + unit];
                float c2 = sigf(gf) * cold + sigf(gi) * ftanh(gg);
                float h2 = sigf(go) * ftanh(c2);
                if (MODE == 0) {
                    hout[gb * HE + unit] = h2;
                    cout[gb * HE + unit] = c2;
                    if (L) g_Xenc[((size_t)gb * T + t) * HE + unit] = h2;
                } else {
                    dcout[gb * 512 + unit] = h2;
                    dcout[gb * 512 + 256 + unit] = c2;
                }
            }
        }
    }
}

// ---------------- tf32 plain GEMM, N=256 (xenc_proj and q) ----------------
// mode 0: xproj = Xenc @ Wxp + da1b   (M = B*T, K = 256)
// mode 1: q     = [d|c] @ Wq          (M = B,   K = 512)
__global__ __launch_bounds__(256) void gemm256_mma_kernel(int mode, int pin,
                                                          const float* __restrict__ bias) {
    const float* Aptr;
    const float* Wptr;
    float* Cptr;
    int lda, NC;
    if (mode == 0) { Aptr = g_Xenc;    Wptr = g_Wxp; Cptr = g_xproj; lda = 256; NC = 16; }
    else           { Aptr = g_dc[pin]; Wptr = g_Wq;  Cptr = g_q;     lda = 512; NC = 32; }

    __shared__ __align__(16) float As[2][ABUF];
    __shared__ __align__(16) float Bs[2][BBUF];

    int tid = threadIdx.x;
    int lane = tid & 31;
    int wid = tid >> 5;
    int wm = wid & 3, wn = wid >> 2;
    int lq = lane & 3, lr = lane >> 2;
    int row0 = blockIdx.x * BM;
    int col0 = blockIdx.y * BN;
    int cg = col0 >> 6;

    int ak = tid & 15;
    int ar0 = tid >> 4;
    int akf = ak >> 3, akq = ak & 7;
    int alane = ((ar0 & 7) << 2) + (akq & 3);
    int aslot = ((akq >> 2) & 1) * 2 + ((ar0 >> 3) & 1);
    int abase = akf * AKF + alane * 4 + aslot;

    float acc[2][4][4] = {};
    float avp[8];
    float4 bvp;

    auto loadChunk = [&](int kc) {
        int k = kc * BK + ak;
#pragma unroll
        for (int i = 0; i < 8; ++i)
            avp[i] = Aptr[(size_t)(row0 + ar0 + 16 * i) * lda + k];
        bvp = *(const float4*)&Wptr[((size_t)(kc * 4 + cg) << 10) + (tid << 2)];
    };
    auto storeChunk = [&](int buf) {
#pragma unroll
        for (int i = 0; i < 8; ++i)
            As[buf][abase + i * 128] = avp[i];
        *(float4*)&Bs[buf][tid << 2] = bvp;
    };
    auto compute = [&](int buf) {
        const float* as = As[buf];
        const float* bs = Bs[buf];
#pragma unroll
        for (int kf = 0; kf < 2; ++kf) {
            float4 afr[2];
            float2 bfr[4];
#pragma unroll
            for (int mi = 0; mi < 2; ++mi)
                afr[mi] = *(const float4*)&as[kf * AKF + (wm * 2 + mi) * 128 + lane * 4];
#pragma unroll
            for (int ni = 0; ni < 4; ++ni)
                bfr[ni] = *(const float2*)&bs[kf * 512 + (wn * 4 + ni) * 64 + lane * 2];
#pragma unroll
            for (int mi = 0; mi < 2; ++mi)
#pragma unroll
                for (int ni = 0; ni < 4; ++ni)
                    mma_tf32(acc[mi][ni], (const unsigned*)&afr[mi], (const unsigned*)&bfr[ni]);
        }
    };

    loadChunk(0);
    storeChunk(0);
    __syncthreads();
#pragma unroll 1
    for (int kc = 0; kc < NC; ++kc) {
        int cur = kc & 1;
        if (kc + 1 < NC) loadChunk(kc + 1);
        compute(cur);
        if (kc + 1 < NC) storeChunk(cur ^ 1);
        __syncthreads();
    }

#pragma unroll
    for (int mi = 0; mi < 2; ++mi) {
#pragma unroll
        for (int half = 0; half < 2; ++half) {
            int gb = row0 + wm * 32 + mi * 16 + half * 8 + lr;
#pragma unroll
            for (int ni = 0; ni < 4; ++ni) {
                int col = col0 + wn * 32 + ni * 8 + 2 * lq;
                float v0 = acc[mi][ni][half * 2 + 0] + (bias ? bias[col] : 0.f);
                float v1 = acc[mi][ni][half * 2 + 1] + (bias ? bias[col + 1] : 0.f);
                *(float2*)&Cptr[(size_t)gb * HE + col] = make_float2(v0, v1);
            }
        }
    }
}

// ---------------- decoder attention (row-wise fused) ----------------------
__global__ __launch_bounds__(256) void dec_attn_kernel(const float* __restrict__ yprev,
                                                       const float* __restrict__ a2w,
                                                       const float* __restrict__ a2b,
                                                       const float* __restrict__ fcw,
                                                       const float* __restrict__ fcb, int t) {
    int b = blockIdx.x;
    int h = threadIdx.x;
    float qh = g_q[b * HE + h];
    float w = a2w[h];
    const float* xp = g_xproj + (size_t)(b * T) * HE + h;
    float sloc[T];
#pragma unroll
    for (int tt = 0; tt < T; ++tt) sloc[tt] = ftanh(xp[tt * HE] + qh) * w;

    __shared__ float part[8][T];
    __shared__ float beta[T];
    int lane = h & 31, wid = h >> 5;
#pragma unroll
    for (int tt = 0; tt < T; ++tt) {
        float v = sloc[tt];
        for (int o = 16; o > 0; o >>= 1) v += __shfl_down_sync(0xFFFFFFFFu, v, o);
        if (!lane) part[wid][tt] = v;
    }
    __syncthreads();
    if (h == 0) {
        float sc[T];
        float mx = -1e30f;
#pragma unroll
        for (int tt = 0; tt < T; ++tt) {
            float s = a2b[0];
#pragma unroll
            for (int w8 = 0; w8 < 8; ++w8) s += part[w8][tt];
            sc[tt] = s;
            mx = fmaxf(mx, s);
        }
        float sum = 0.f;
#pragma unroll
        for (int tt = 0; tt < T; ++tt) { sc[tt] = __expf(sc[tt] - mx); sum += sc[tt]; }
        float inv = __fdividef(1.f, sum);
#pragma unroll
        for (int tt = 0; tt < T; ++tt) beta[tt] = sc[tt] * inv;
    }
    __syncthreads();
    const float* xe = g_Xenc + (size_t)(b * T) * HE + h;
    float ctx = 0.f;
#pragma unroll
    for (int tt = 0; tt < T; ++tt) ctx += beta[tt] * xe[tt * HE];
    g_ctx[b * HE + h] = ctx;
    float yv = ctx * fcw[h];
    for (int o = 16; o > 0; o >>= 1) yv += __shfl_down_sync(0xFFFFFFFFu, yv, o);
    __syncthreads();
    if (!lane) part[wid][0] = yv;
    __syncthreads();
    if (h == 0) {
        float s = 0.f;
#pragma unroll
        for (int w8 = 0; w8 < 8; ++w8) s += part[w8][0];
        g_yt[b] = s + yprev[b * T + t] * fcw[HE] + fcb[0];
    }
}

// ---------------- final output --------------------------------------------
__global__ void final_kernel(const float* __restrict__ ffw, const float* __restrict__ ffb,
                             float* __restrict__ out, int pin) {
    int gtid = blockIdx.x * blockDim.x + threadIdx.x;
    int warp = gtid >> 5;
    int lane = gtid & 31;
    if (warp >= B) return;
    const float* d = g_dc[pin] + warp * 512;
    const float* ctx = g_ctx + warp * HE;
    float s = 0.f;
    for (int h = lane; h < HE; h += 32) s += d[h] * ffw[h] + ctx[h] * ffw[HE + h];
    for (int o = 16; o > 0; o >>= 1) s += __shfl_down_sync(0xFFFFFFFFu, s, o);
    if (!lane) out[warp] = s + ffb[0];
}

// ---------------- launch ---------------------------------------------------
extern "C" void kernel_launch(void* const* d_in, const int* in_sizes, int n_in,
                              void* d_out, int out_size) {
    const float* X      = (const float*)d_in[0];
    const float* yprev  = (const float*)d_in[1];
    const float* e1w    = (const float*)d_in[2];
    const float* e1b    = (const float*)d_in[3];
    const float* e2w    = (const float*)d_in[4];
    const float* e2b    = (const float*)d_in[5];
    const float* l1_wih = (const float*)d_in[6];
    const float* l1_whh = (const float*)d_in[7];
    const float* l1_b   = (const float*)d_in[8];
    const float* l2_wih = (const float*)d_in[9];
    const float* l2_whh = (const float*)d_in[10];
    const float* l2_b   = (const float*)d_in[11];
    const float* da1w   = (const float*)d_in[12];
    const float* da1b   = (const float*)d_in[13];
    const float* da2w   = (const float*)d_in[14];
    const float* da2b   = (const float*)d_in[15];
    const float* dlwih  = (const float*)d_in[16];
    const float* dlwhh  = (const float*)d_in[17];
    const float* dlb    = (const float*)d_in[18];
    const float* fcw    = (const float*)d_in[19];
    const float* fcb    = (const float*)d_in[20];
    const float* ffw    = (const float*)d_in[21];
    const float* ffb    = (const float*)d_in[22];
    float* out = (float*)d_out;

    pack_kernel<<<512, 256>>>(l1_wih, l1_whh, l1_b, l2_wih, l2_whh, l2_b,
                              dlwih, dlwhh, dlb, da1w);
    init_kernel<<<512, 256>>>();
    attn_kernel<<<B, 128>>>(X, yprev, e1w, e1b, e2w, e2b);

    for (int t = 0; t < T; ++t)
        lstm_mma_kernel<0><<<dim3(B / BM, NG / BN, 2), 256>>>(X, t, t & 1, (t + 1) & 1);

    // xenc_proj over all (b, t)
    gemm256_mma_kernel<<<dim3(B * T / BM, HE / BN), 256>>>(0, 0, da1b);

    for (int t = 0; t < T; ++t) {
        gemm256_mma_kernel<<<dim3(B / BM, HE / BN), 256>>>(1, t & 1, nullptr);
        dec_attn_kernel<<<B, 256>>>(yprev, da2w, da2b, fcw, fcb, t);
        lstm_mma_kernel<1><<<dim3(B / BM, NG / BN), 256>>>(nullptr, 0, t & 1, (t + 1) & 1);
    }

    final_kernel<<<B * 32 / 256, 256>>>(ffw, ffb, out, T & 1);
}

// round 10
// speedup vs baseline: 2.3656x; 1.0896x over previous
#include <cuda_runtime.h>

#define B 8192
#define T 15
#define D 81
#define HE 256
#define NG 1024
#define XP 96         // padded x-width for encoder
#define KENC_PAD 352  // 96 (x, padded) + 256 (h)
#define KDEC_PAD 272  // 256 (d) + 16 (y + pad)

#define BM 128
#define BN 64
#define BK 16
#define AKF 1040      // per-kf A block: 8 mt * 32 unit * 4 + 16 pad (16B aligned)
#define ABUF (2 * AKF)
#define BBUF 1024     // 2 kf * 8 nt * 32 lane * 2 slot

// ---------------- scratch (static device memory; no allocations) ----------
__device__ float g_A1[B * D];
__device__ float g_A12[B * D];
__device__ float g_Xs[2][T * B * XP];       // [L][t][b][96]: scaled, zero-padded X
__device__ float g_Wenc[2][KENC_PAD * NG];  // fragment-packed (see frag_idx)
__device__ float g_benc[2][NG];
__device__ float g_Wdec[KDEC_PAD * NG];     // fragment-packed
__device__ float g_bdec[NG];
__device__ float g_Wq[512 * HE];            // fragment-packed; k<256 -> W1d, else W1c
__device__ float g_Wxp[HE * HE];            // fragment-packed; [k][n] = W1x[n][k]
__device__ float g_h1[2][B * HE];
__device__ float g_c1[2][B * HE];
__device__ float g_h2[2][B * HE];
__device__ float g_c2[2][B * HE];
__device__ float g_Xenc[B * T * HE];        // [b][t][h]
__device__ float g_xproj[B * T * HE];
__device__ float g_dc[2][B * 512];          // decoder state [d | c]
__device__ float g_q[B * HE];
__device__ float g_yt[B];
__device__ float g_ctx[B * HE];

// ---------------- math helpers -------------------------------------------
__device__ __forceinline__ float sigf(float x) {
    return __fdividef(1.f, 1.f + __expf(-x));
}
__device__ __forceinline__ float ftanh(float x) {
    float e = __expf(-2.f * fabsf(x));
    float r = __fdividef(1.f - e, 1.f + e);
    return copysignf(r, x);
}
__device__ __forceinline__ void mma_tf32(float* c, const unsigned* a, const unsigned* b) {
    asm volatile(
        "mma.sync.aligned.m16n8k8.row.col.f32.tf32.tf32.f32 "
        "{%0,%1,%2,%3}, {%4,%5,%6,%7}, {%8,%9}, {%0,%1,%2,%3};\n"
        : "+f"(c[0]), "+f"(c[1]), "+f"(c[2]), "+f"(c[3])
        : "r"(a[0]), "r"(a[1]), "r"(a[2]), "r"(a[3]), "r"(b[0]), "r"(b[1]));
}

// Fragment-packed B-weight index (unchanged layout).
__device__ __forceinline__ size_t frag_idx(int k, int c, int ncg) {
    int kc = k >> 4, kf = (k >> 3) & 1, kq = k & 7;
    int cg = c >> 6, nt = (c & 63) >> 3;
    int lane = ((c & 7) << 2) + (kq & 3);
    int slot = (kq >> 2) & 1;
    return ((((size_t)(kc * ncg + cg) * 2 + kf) * 8 + nt) * 64) + lane * 2 + slot;
}

// Packed column mapping for LSTM weights (col -> original row n)
__device__ __forceinline__ int lstm_src_n(int c) {
    int g32 = c >> 5, p = c & 31;
    int u = (g32 << 3) + ((p & 15) >> 1);
    int gate = ((p & 16) ? 2 : 0) + (p & 1);
    return gate * HE + u;
}

// ---------------- weight packing ------------------------------------------
__global__ void pack_kernel(const float* __restrict__ l1_wih, const float* __restrict__ l1_whh,
                            const float* __restrict__ l1_b,
                            const float* __restrict__ l2_wih, const float* __restrict__ l2_whh,
                            const float* __restrict__ l2_b,
                            const float* __restrict__ dl_wih, const float* __restrict__ dl_whh,
                            const float* __restrict__ dl_b,
                            const float* __restrict__ da1w) {
    int stride = gridDim.x * blockDim.x;
    int idx0 = blockIdx.x * blockDim.x + threadIdx.x;
    // Encoder: k order = [x 0..95 (81 real) | h 0..255]
    for (int i = idx0; i < KENC_PAD * NG; i += stride) {
        int k = i >> 10, col = i & 1023;
        int n = lstm_src_n(col);
        float v1 = 0.f, v2 = 0.f;
        if (k < D)        { v1 = l1_wih[n * D + k];             v2 = l2_wih[n * D + k]; }
        else if (k >= XP) { v1 = l1_whh[n * HE + (k - XP)];     v2 = l2_whh[n * HE + (k - XP)]; }
        size_t fi = frag_idx(k, col, 16);
        g_Wenc[0][fi] = v1;
        g_Wenc[1][fi] = v2;
    }
    // Decoder: k order = [d 0..255 | y at 256 | pad]
    for (int i = idx0; i < KDEC_PAD * NG; i += stride) {
        int k = i >> 10, col = i & 1023;
        int n = lstm_src_n(col);
        float v = 0.f;
        if (k < 256)       v = dl_whh[n * HE + k];
        else if (k == 256) v = dl_wih[n];
        g_Wdec[frag_idx(k, col, 16)] = v;
    }
    for (int i = idx0; i < 512 * HE; i += stride) {
        int k = i >> 8, n = i & 255;
        float v = (k < HE) ? da1w[n * 768 + k] : da1w[n * 768 + 256 + (k - HE)];
        g_Wq[frag_idx(k, n, 4)] = v;
    }
    for (int i = idx0; i < HE * HE; i += stride) {
        int k = i >> 8, n = i & 255;
        g_Wxp[frag_idx(k, n, 4)] = da1w[n * 768 + 512 + k];
    }
    for (int i = idx0; i < NG; i += stride) {
        int n = lstm_src_n(i);
        g_benc[0][i] = l1_b[n];
        g_benc[1][i] = l2_b[n];
        g_bdec[i]    = dl_b[n];
    }
}

__global__ void init_kernel() {
    int stride = gridDim.x * blockDim.x;
    int i0 = blockIdx.x * blockDim.x + threadIdx.x;
    for (int j = i0; j < B * HE; j += stride) {
        g_h1[0][j] = 0.f; g_c1[0][j] = 0.f;
        g_h2[0][j] = 0.f; g_c2[0][j] = 0.f;
    }
    for (int j = i0; j < B * 512; j += stride) g_dc[0][j] = 0.f;
}

// ---------------- input attention (a1, a1*a2) — state-independent ---------
__global__ void attn_kernel(const float* __restrict__ X, const float* __restrict__ yprev,
                            const float* __restrict__ e1w, const float* __restrict__ e1b,
                            const float* __restrict__ e2w, const float* __restrict__ e2b) {
    int b = blockIdx.x;
    int j = threadIdx.x;
    float v1 = -1e30f, v2 = -1e30f;
    if (j < D) {
        const float* xb = X + (size_t)b * T * D + j;
        float s1 = 0.f, s2 = 0.f;
#pragma unroll
        for (int t = 0; t < T; ++t) {
            float x = xb[t * D];
            s1 += x * e1w[2 * HE + t];
            s2 += x * e2w[2 * HE + t];
        }
        float yw = 0.f;
#pragma unroll
        for (int t = 0; t < T; ++t) yw += yprev[b * T + t] * e2w[2 * HE + T + t];
        v1 = s1 + e1b[0];
        v2 = s2 + yw + e2b[0];
    }
    __shared__ float red1[128], red2[128];
    red1[j] = v1; red2[j] = v2;
    __syncthreads();
    for (int o = 64; o > 0; o >>= 1) {
        if (j < o) {
            red1[j] = fmaxf(red1[j], red1[j + o]);
            red2[j] = fmaxf(red2[j], red2[j + o]);
        }
        __syncthreads();
    }
    float m1 = red1[0], m2 = red2[0];
    __syncthreads();
    float e1v = (j < D) ? __expf(v1 - m1) : 0.f;
    float e2v = (j < D) ? __expf(v2 - m2) : 0.f;
    red1[j] = e1v; red2[j] = e2v;
    __syncthreads();
    for (int o = 64; o > 0; o >>= 1) {
        if (j < o) { red1[j] += red1[j + o]; red2[j] += red2[j + o]; }
        __syncthreads();
    }
    if (j < D) {
        float a1 = __fdividef(e1v, red1[0]);
        float a2 = __fdividef(e2v, red2[0]);
        g_A1[b * D + j]  = a1;
        g_A12[b * D + j] = a1 * a2;
    }
}

// ---------------- scaled & padded X precompute -----------------------------
// g_Xs[L][t][b][j] = (j < 81 ? scale_L[b][j] * X[b][t][j] : 0)
__global__ void prep_xs_kernel(const float* __restrict__ X) {
    int y = blockIdx.y;            // 0..29
    int L = y / T, t = y % T;
    const float* scale = L ? g_A12 : g_A1;
    float* out = &g_Xs[L][(size_t)t * B * XP];
    int i = blockIdx.x * blockDim.x + threadIdx.x;   // over B*XP
    if (i >= B * XP) return;
    int b = i / XP, j = i - b * XP;
    float v = 0.f;
    if (j < D) v = scale[b * D + j] * X[((size_t)b * T + t) * D + j];
    out[i] = v;
}

// ============= tf32 tensor-core GEMM + fused LSTM epilogue =================
// MODE 0: encoder step (grid.z selects layer); MODE 1: decoder LSTM
template <int MODE>
__global__ __launch_bounds__(256) void lstm_mma_kernel(int t, int pin, int pout) {
    const float* xsrc = nullptr;
    const float* hin = nullptr;
    const float* cin = nullptr;
    float* hout = nullptr;
    float* cout = nullptr;
    const float* Wg;
    const float* bias;
    const float* dcin = nullptr;
    float* dcout = nullptr;
    int L = 0;
    int NC;
    if (MODE == 0) {
        L = blockIdx.z;
        xsrc = &g_Xs[L][(size_t)t * B * XP];
        hin = L ? g_h2[pin] : g_h1[pin];
        cin = L ? g_c2[pin] : g_c1[pin];
        hout = L ? g_h2[pout] : g_h1[pout];
        cout = L ? g_c2[pout] : g_c1[pout];
        Wg = g_Wenc[L];
        bias = g_benc[L];
        NC = KENC_PAD / BK;      // 22
    } else {
        dcin = g_dc[pin];
        dcout = g_dc[pout];
        Wg = g_Wdec;
        bias = g_bdec;
        NC = KDEC_PAD / BK;      // 17
    }

    __shared__ __align__(16) float As[2][ABUF];
    __shared__ __align__(16) float Bs[2][BBUF];

    int tid = threadIdx.x;
    int lane = tid & 31;
    int wid = tid >> 5;
    int wm = wid & 3, wn = wid >> 2;      // 4 row-warps x 2 col-warps
    int lq = lane & 3, lr = lane >> 2;
    int row0 = blockIdx.x * BM;
    int col0 = blockIdx.y * BN;
    int cg = col0 >> 6;

    // A loader: thread = (row, kf-half); loads 8 consecutive k (2x float4)
    int arow = tid >> 1;                  // 0..127
    int akf = tid & 1;
    int agb = row0 + arow;
    int art = arow & 15, amt = arow >> 4;
    int ar7 = art & 7, asb = art >> 3;
    int abase = akf * AKF + amt * 128;
    // per-kq unit: ar7*4 + (kq3 ^ (ar7>>1)); slot = (kq>>2)*2 + asb
    int axor = ar7 >> 1;

    const float* xrow = (MODE == 0) ? (xsrc + (size_t)agb * XP) : nullptr;
    const float* hrow = (MODE == 0) ? (hin + (size_t)agb * HE) : (dcin + (size_t)agb * 512);

    float acc[2][4][4] = {};
    float4 f4a, f4b;

    auto loadChunk = [&](int kc) {
        if (MODE == 0) {
            if (kc < 6) {
                const float* p = xrow + kc * 16 + akf * 8;
                f4a = *(const float4*)p;
                f4b = *(const float4*)(p + 4);
            } else {
                const float* p = hrow + (kc - 6) * 16 + akf * 8;
                f4a = *(const float4*)p;
                f4b = *(const float4*)(p + 4);
            }
        } else {
            if (kc < 16) {
                const float* p = hrow + kc * 16 + akf * 8;
                f4a = *(const float4*)p;
                f4b = *(const float4*)(p + 4);
            } else {
                f4a = make_float4(akf == 0 ? g_yt[agb] : 0.f, 0.f, 0.f, 0.f);
                f4b = make_float4(0.f, 0.f, 0.f, 0.f);
            }
        }
    };
    auto storeChunk = [&](int buf) {
        float v[8] = {f4a.x, f4a.y, f4a.z, f4a.w, f4b.x, f4b.y, f4b.z, f4b.w};
        float* as = As[buf] + abase;
#pragma unroll
        for (int kq = 0; kq < 8; ++kq) {
            int unit = ar7 * 4 + ((kq & 3) ^ axor);
            int slot = (kq >> 2) * 2 + asb;
            as[unit * 4 + slot] = v[kq];
        }
        *(float4*)&Bs[buf][tid << 2] =
            *(const float4*)&Wg[((size_t)0) + (((size_t)0) /*dummy*/)] ;  // replaced below
    };
    // B copy handled separately to keep lambda simple
    const float* bsrc_base = Wg;

    auto loadB = [&](int kc) -> float4 {
        return *(const float4*)&bsrc_base[((size_t)(kc * ((MODE == 0) ? 16 : 16) + cg) << 10) + (tid << 2)];
    };

    float4 bvp;
    auto compute = [&](int buf) {
        const float* as = As[buf];
        const float* bs = Bs[buf];
        int aoff = (lr * 4 + (lq ^ (lr >> 1))) * 4;
#pragma unroll
        for (int kf = 0; kf < 2; ++kf) {
            float4 afr[2];
            float2 bfr[4];
#pragma unroll
            for (int mi = 0; mi < 2; ++mi)
                afr[mi] = *(const float4*)&as[kf * AKF + (wm * 2 + mi) * 128 + aoff];
#pragma unroll
            for (int ni = 0; ni < 4; ++ni)
                bfr[ni] = *(const float2*)&bs[kf * 512 + (wn * 4 + ni) * 64 + lane * 2];
#pragma unroll
            for (int mi = 0; mi < 2; ++mi)
#pragma unroll
                for (int ni = 0; ni < 4; ++ni)
                    mma_tf32(acc[mi][ni], (const unsigned*)&afr[mi], (const unsigned*)&bfr[ni]);
        }
    };

    // prologue
    loadChunk(0);
    bvp = loadB(0);
    {
        float v[8] = {f4a.x, f4a.y, f4a.z, f4a.w, f4b.x, f4b.y, f4b.z, f4b.w};
        float* as = As[0] + abase;
#pragma unroll
        for (int kq = 0; kq < 8; ++kq) {
            int unit = ar7 * 4 + ((kq & 3) ^ axor);
            int slot = (kq >> 2) * 2 + asb;
            as[unit * 4 + slot] = v[kq];
        }
        *(float4*)&Bs[0][tid << 2] = bvp;
    }
    __syncthreads();
#pragma unroll 1
    for (int kc = 0; kc < NC; ++kc) {
        int cur = kc & 1;
        if (kc + 1 < NC) { loadChunk(kc + 1); bvp = loadB(kc + 1); }
        compute(cur);
        if (kc + 1 < NC) {
            float v[8] = {f4a.x, f4a.y, f4a.z, f4a.w, f4b.x, f4b.y, f4b.z, f4b.w};
            float* as = As[cur ^ 1] + abase;
#pragma unroll
            for (int kq = 0; kq < 8; ++kq) {
                int unit = ar7 * 4 + ((kq & 3) ^ axor);
                int slot = (kq >> 2) * 2 + asb;
                as[unit * 4 + slot] = v[kq];
            }
            *(float4*)&Bs[cur ^ 1][tid << 2] = bvp;
        }
        __syncthreads();
    }

    // ---- fused LSTM epilogue on gate-interleaved columns ----
    int cbase = col0 + wn * 32;
#pragma unroll
    for (int upair = 0; upair < 2; ++upair) {
        int unit = (cbase >> 2) + upair * 4 + lq;
        float bI = bias[cbase + upair * 8 + 2 * lq];
        float bF = bias[cbase + upair * 8 + 2 * lq + 1];
        float bG = bias[cbase + 16 + upair * 8 + 2 * lq];
        float bO = bias[cbase + 16 + upair * 8 + 2 * lq + 1];
#pragma unroll
        for (int mi = 0; mi < 2; ++mi) {
#pragma unroll
            for (int half = 0; half < 2; ++half) {
                int gb = row0 + wm * 32 + mi * 16 + half * 8 + lr;
                float gi = acc[mi][upair][half * 2 + 0] + bI;
                float gf = acc[mi][upair][half * 2 + 1] + bF;
                float gg = acc[mi][2 + upair][half * 2 + 0] + bG;
                float go = acc[mi][2 + upair][half * 2 + 1] + bO;
                float cold = (MODE == 0) ? cin[gb * HE + unit]
                                         : dcin[gb * 512 + 256 + unit];
                float c2 = sigf(gf) * cold + sigf(gi) * ftanh(gg);
                float h2 = sigf(go) * ftanh(c2);
                if (MODE == 0) {
                    hout[gb * HE + unit] = h2;
                    cout[gb * HE + unit] = c2;
                    if (L) g_Xenc[((size_t)gb * T + t) * HE + unit] = h2;
                } else {
                    dcout[gb * 512 + unit] = h2;
                    dcout[gb * 512 + 256 + unit] = c2;
                }
            }
        }
    }
}

// ---------------- tf32 plain GEMM, N=256 (xenc_proj and q) ----------------
// mode 0: xproj = Xenc @ Wxp + da1b   (M = B*T, K = 256)
// mode 1: q     = [d|c] @ Wq          (M = B,   K = 512)
__global__ __launch_bounds__(256) void gemm256_mma_kernel(int mode, int pin,
                                                          const float* __restrict__ bias) {
    const float* Aptr;
    const float* Wptr;
    float* Cptr;
    int lda, NC;
    if (mode == 0) { Aptr = g_Xenc;    Wptr = g_Wxp; Cptr = g_xproj; lda = 256; NC = 16; }
    else           { Aptr = g_dc[pin]; Wptr = g_Wq;  Cptr = g_q;     lda = 512; NC = 32; }

    __shared__ __align__(16) float As[2][ABUF];
    __shared__ __align__(16) float Bs[2][BBUF];

    int tid = threadIdx.x;
    int lane = tid & 31;
    int wid = tid >> 5;
    int wm = wid & 3, wn = wid >> 2;
    int lq = lane & 3, lr = lane >> 2;
    int row0 = blockIdx.x * BM;
    int col0 = blockIdx.y * BN;
    int cg = col0 >> 6;

    int arow = tid >> 1;
    int akf = tid & 1;
    int art = arow & 15, amt = arow >> 4;
    int ar7 = art & 7, asb = art >> 3;
    int abase = akf * AKF + amt * 128;
    int axor = ar7 >> 1;
    const float* arowp = Aptr + (size_t)(row0 + arow) * lda + akf * 8;

    float acc[2][4][4] = {};
    float4 f4a, f4b, bvp;

    auto loadChunk = [&](int kc) {
        const float* p = arowp + kc * 16;
        f4a = *(const float4*)p;
        f4b = *(const float4*)(p + 4);
        bvp = *(const float4*)&Wptr[((size_t)(kc * 4 + cg) << 10) + (tid << 2)];
    };
    auto storeChunk = [&](int buf) {
        float v[8] = {f4a.x, f4a.y, f4a.z, f4a.w, f4b.x, f4b.y, f4b.z, f4b.w};
        float* as = As[buf] + abase;
#pragma unroll
        for (int kq = 0; kq < 8; ++kq) {
            int unit = ar7 * 4 + ((kq & 3) ^ axor);
            int slot = (kq >> 2) * 2 + asb;
            as[unit * 4 + slot] = v[kq];
        }
        *(float4*)&Bs[buf][tid << 2] = bvp;
    };
    auto compute = [&](int buf) {
        const float* as = As[buf];
        const float* bs = Bs[buf];
        int aoff = (lr * 4 + (lq ^ (lr >> 1))) * 4;
#pragma unroll
        for (int kf = 0; kf < 2; ++kf) {
            float4 afr[2];
            float2 bfr[4];
#pragma unroll
            for (int mi = 0; mi < 2; ++mi)
                afr[mi] = *(const float4*)&as[kf * AKF + (wm * 2 + mi) * 128 + aoff];
#pragma unroll
            for (int ni = 0; ni < 4; ++ni)
                bfr[ni] = *(const float2*)&bs[kf * 512 + (wn * 4 + ni) * 64 + lane * 2];
#pragma unroll
            for (int mi = 0; mi < 2; ++mi)
#pragma unroll
                for (int ni = 0; ni < 4; ++ni)
                    mma_tf32(acc[mi][ni], (const unsigned*)&afr[mi], (const unsigned*)&bfr[ni]);
        }
    };

    loadChunk(0);
    storeChunk(0);
    __syncthreads();
#pragma unroll 1
    for (int kc = 0; kc < NC; ++kc) {
        int cur = kc & 1;
        if (kc + 1 < NC) loadChunk(kc + 1);
        compute(cur);
        if (kc + 1 < NC) storeChunk(cur ^ 1);
        __syncthreads();
    }

#pragma unroll
    for (int mi = 0; mi < 2; ++mi) {
#pragma unroll
        for (int half = 0; half < 2; ++half) {
            int gb = row0 + wm * 32 + mi * 16 + half * 8 + lr;
#pragma unroll
            for (int ni = 0; ni < 4; ++ni) {
                int col = col0 + wn * 32 + ni * 8 + 2 * lq;
                float v0 = acc[mi][ni][half * 2 + 0] + (bias ? bias[col] : 0.f);
                float v1 = acc[mi][ni][half * 2 + 1] + (bias ? bias[col + 1] : 0.f);
                *(float2*)&Cptr[(size_t)gb * HE + col] = make_float2(v0, v1);
            }
        }
    }
}

// ---------------- decoder attention (row-wise fused) ----------------------
__global__ __launch_bounds__(256) void dec_attn_kernel(const float* __restrict__ yprev,
                                                       const float* __restrict__ a2w,
                                                       const float* __restrict__ a2b,
                                                       const float* __restrict__ fcw,
                                                       const float* __restrict__ fcb, int t) {
    int b = blockIdx.x;
    int h = threadIdx.x;
    float qh = g_q[b * HE + h];
    float w = a2w[h];
    const float* xp = g_xproj + (size_t)(b * T) * HE + h;
    float sloc[T];
#pragma unroll
    for (int tt = 0; tt < T; ++tt) sloc[tt] = ftanh(xp[tt * HE] + qh) * w;

    __shared__ float part[8][T];
    __shared__ float beta[T];
    int lane = h & 31, wid = h >> 5;
#pragma unroll
    for (int tt = 0; tt < T; ++tt) {
        float v = sloc[tt];
        for (int o = 16; o > 0; o >>= 1) v += __shfl_down_sync(0xFFFFFFFFu, v, o);
        if (!lane) part[wid][tt] = v;
    }
    __syncthreads();
    if (h == 0) {
        float sc[T];
        float mx = -1e30f;
#pragma unroll
        for (int tt = 0; tt < T; ++tt) {
            float s = a2b[0];
#pragma unroll
            for (int w8 = 0; w8 < 8; ++w8) s += part[w8][tt];
            sc[tt] = s;
            mx = fmaxf(mx, s);
        }
        float sum = 0.f;
#pragma unroll
        for (int tt = 0; tt < T; ++tt) { sc[tt] = __expf(sc[tt] - mx); sum += sc[tt]; }
        float inv = __fdividef(1.f, sum);
#pragma unroll
        for (int tt = 0; tt < T; ++tt) beta[tt] = sc[tt] * inv;
    }
    __syncthreads();
    const float* xe = g_Xenc + (size_t)(b * T) * HE + h;
    float ctx = 0.f;
#pragma unroll
    for (int tt = 0; tt < T; ++tt) ctx += beta[tt] * xe[tt * HE];
    g_ctx[b * HE + h] = ctx;
    float yv = ctx * fcw[h];
    for (int o = 16; o > 0; o >>= 1) yv += __shfl_down_sync(0xFFFFFFFFu, yv, o);
    __syncthreads();
    if (!lane) part[wid][0] = yv;
    __syncthreads();
    if (h == 0) {
        float s = 0.f;
#pragma unroll
        for (int w8 = 0; w8 < 8; ++w8) s += part[w8][0];
        g_yt[b] = s + yprev[b * T + t] * fcw[HE] + fcb[0];
    }
}

// ---------------- final output --------------------------------------------
__global__ void final_kernel(const float* __restrict__ ffw, const float* __restrict__ ffb,
                             float* __restrict__ out, int pin) {
    int gtid = blockIdx.x * blockDim.x + threadIdx.x;
    int warp = gtid >> 5;
    int lane = gtid & 31;
    if (warp >= B) return;
    const float* d = g_dc[pin] + warp * 512;
    const float* ctx = g_ctx + warp * HE;
    float s = 0.f;
    for (int h = lane; h < HE; h += 32) s += d[h] * ffw[h] + ctx[h] * ffw[HE + h];
    for (int o = 16; o > 0; o >>= 1) s += __shfl_down_sync(0xFFFFFFFFu, s, o);
    if (!lane) out[warp] = s + ffb[0];
}

// ---------------- launch ---------------------------------------------------
extern "C" void kernel_launch(void* const* d_in, const int* in_sizes, int n_in,
                              void* d_out, int out_size) {
    const float* X      = (const float*)d_in[0];
    const float* yprev  = (const float*)d_in[1];
    const float* e1w    = (const float*)d_in[2];
    const float* e1b    = (const float*)d_in[3];
    const float* e2w    = (const float*)d_in[4];
    const float* e2b    = (const float*)d_in[5];
    const float* l1_wih = (const float*)d_in[6];
    const float* l1_whh = (const float*)d_in[7];
    const float* l1_b   = (const float*)d_in[8];
    const float* l2_wih = (const float*)d_in[9];
    const float* l2_whh = (const float*)d_in[10];
    const float* l2_b   = (const float*)d_in[11];
    const float* da1w   = (const float*)d_in[12];
    const float* da1b   = (const float*)d_in[13];
    const float* da2w   = (const float*)d_in[14];
    const float* da2b   = (const float*)d_in[15];
    const float* dlwih  = (const float*)d_in[16];
    const float* dlwhh  = (const float*)d_in[17];
    const float* dlb    = (const float*)d_in[18];
    const float* fcw    = (const float*)d_in[19];
    const float* fcb    = (const float*)d_in[20];
    const float* ffw    = (const float*)d_in[21];
    const float* ffb    = (const float*)d_in[22];
    float* out = (float*)d_out;

    pack_kernel<<<512, 256>>>(l1_wih, l1_whh, l1_b, l2_wih, l2_whh, l2_b,
                              dlwih, dlwhh, dlb, da1w);
    init_kernel<<<512, 256>>>();
    attn_kernel<<<B, 128>>>(X, yprev, e1w, e1b, e2w, e2b);
    prep_xs_kernel<<<dim3((B * XP + 255) / 256, 2 * T), 256>>>(X);

    for (int t = 0; t < T; ++t)
        lstm_mma_kernel<0><<<dim3(B / BM, NG / BN, 2), 256>>>(t, t & 1, (t + 1) & 1);

    // xenc_proj over all (b, t)
    gemm256_mma_kernel<<<dim3(B * T / BM, HE / BN), 256>>>(0, 0, da1b);

    for (int t = 0; t < T; ++t) {
        gemm256_mma_kernel<<<dim3(B / BM, HE / BN), 256>>>(1, t & 1, nullptr);
        dec_attn_kernel<<<B, 256>>>(yprev, da2w, da2b, fcw, fcb, t);
        lstm_mma_kernel<1><<<dim3(B / BM, NG / BN), 256>>>(0, t & 1, (t + 1) & 1);
    }

    final_kernel<<<B * 32 / 256, 256>>>(ffw, ffb, out, T & 1);
}

// round 12
// speedup vs baseline: 3.3352x; 1.4099x over previous
#include <cuda_runtime.h>
#include <cuda_fp16.h>

#define B 8192
#define T 15
#define D 81
#define HE 256
#define NG 1024
#define XP 96         // padded x-width for encoder
#define KENC_PAD 352  // 96 (x, padded) + 256 (h)
#define KDEC_PAD 272  // 256 (d) + 16 (y + pad)

#define BM 128
#define BN 64
#define BK 16
#define AS32 1040     // per-buffer A words: 8 mt * 128 + 16 pad
#define BS32 528      // per-buffer B words: 512 + 16 pad

// ---------------- scratch (static device memory; no allocations) ----------
__device__ float  g_A1[B * D];
__device__ float  g_A12[B * D];
__device__ __half g_Xs16[2][T * B * XP];        // [L][t][b][96] scaled, padded, fp16
__device__ __half g_Wenc16[2][KENC_PAD * NG];   // fragment-packed fp16
__device__ float  g_benc[2][NG];
__device__ __half g_Wdec16[KDEC_PAD * NG];
__device__ float  g_bdec[NG];
__device__ __half g_Wq16[512 * HE];             // k<256 -> W1d, else W1c
__device__ __half g_Wxp16[HE * HE];             // [k][n] = W1x[n][k]
__device__ __half g_h16[2][2][B * HE];          // [L][parity] encoder h (fp16)
__device__ float  g_c1[2][B * HE];
__device__ float  g_c2[2][B * HE];
__device__ float  g_Xenc[B * T * HE];           // fp32 (decoder attention ctx)
__device__ __half g_Xenc16[B * T * HE];         // fp16 (xproj GEMM A)
__device__ float  g_xproj[B * T * HE];
__device__ float  g_dc[2][B * 512];             // decoder state [d | c] fp32
__device__ __half g_dc16[2][B * 512];           // fp16 copy for GEMM A
__device__ float  g_q[B * HE];
__device__ __half g_yt16[B];
__device__ float  g_ctx[B * HE];

// ---------------- math helpers -------------------------------------------
__device__ __forceinline__ float sigf(float x) {
    return __fdividef(1.f, 1.f + __expf(-x));
}
__device__ __forceinline__ float ftanh(float x) {
    float e = __expf(-2.f * fabsf(x));
    float r = __fdividef(1.f - e, 1.f + e);
    return copysignf(r, x);
}
__device__ __forceinline__ void mma_f16(float* c, const int4& a, const int2& b) {
    asm volatile(
        "mma.sync.aligned.m16n8k16.row.col.f32.f16.f16.f32 "
        "{%0,%1,%2,%3}, {%4,%5,%6,%7}, {%8,%9}, {%0,%1,%2,%3};\n"
        : "+f"(c[0]), "+f"(c[1]), "+f"(c[2]), "+f"(c[3])
        : "r"(a.x), "r"(a.y), "r"(a.z), "r"(a.w), "r"(b.x), "r"(b.y));
}

// Fragment-packed fp16 B-weight index for m16n8k16.
// reg b0 = {B[2q][col], B[2q+1][col]}, b1 = {B[2q+8][col], B[2q+9][col]}, col = lane>>2, q = lane&3
__device__ __forceinline__ size_t frag16_idx(int k, int c, int ncg) {
    int block = (k >> 4) * ncg + (c >> 6);
    int nt = (c & 63) >> 3;
    int lane = ((c & 7) << 2) + ((k >> 1) & 3);
    int khalf = (k >> 3) & 1, p = k & 1;
    return (size_t)block * 1024 + nt * 128 + lane * 4 + khalf * 2 + p;
}

// Packed column mapping for LSTM weights (col -> original row n)
__device__ __forceinline__ int lstm_src_n(int c) {
    int g32 = c >> 5, p = c & 31;
    int u = (g32 << 3) + ((p & 15) >> 1);
    int gate = ((p & 16) ? 2 : 0) + (p & 1);
    return gate * HE + u;
}

// ---------------- weight packing ------------------------------------------
__global__ void pack_kernel(const float* __restrict__ l1_wih, const float* __restrict__ l1_whh,
                            const float* __restrict__ l1_b,
                            const float* __restrict__ l2_wih, const float* __restrict__ l2_whh,
                            const float* __restrict__ l2_b,
                            const float* __restrict__ dl_wih, const float* __restrict__ dl_whh,
                            const float* __restrict__ dl_b,
                            const float* __restrict__ da1w) {
    int stride = gridDim.x * blockDim.x;
    int idx0 = blockIdx.x * blockDim.x + threadIdx.x;
    // Encoder: k order = [x 0..95 (81 real) | h 0..255]
    for (int i = idx0; i < KENC_PAD * NG; i += stride) {
        int k = i >> 10, col = i & 1023;
        int n = lstm_src_n(col);
        float v1 = 0.f, v2 = 0.f;
        if (k < D)        { v1 = l1_wih[n * D + k];         v2 = l2_wih[n * D + k]; }
        else if (k >= XP) { v1 = l1_whh[n * HE + (k - XP)]; v2 = l2_whh[n * HE + (k - XP)]; }
        size_t fi = frag16_idx(k, col, 16);
        g_Wenc16[0][fi] = __float2half_rn(v1);
        g_Wenc16[1][fi] = __float2half_rn(v2);
    }
    // Decoder: k order = [d 0..255 | y at 256 | pad]
    for (int i = idx0; i < KDEC_PAD * NG; i += stride) {
        int k = i >> 10, col = i & 1023;
        int n = lstm_src_n(col);
        float v = 0.f;
        if (k < 256)       v = dl_whh[n * HE + k];
        else if (k == 256) v = dl_wih[n];
        g_Wdec16[frag16_idx(k, col, 16)] = __float2half_rn(v);
    }
    for (int i = idx0; i < 512 * HE; i += stride) {
        int k = i >> 8, n = i & 255;
        float v = (k < HE) ? da1w[n * 768 + k] : da1w[n * 768 + 256 + (k - HE)];
        g_Wq16[frag16_idx(k, n, 4)] = __float2half_rn(v);
    }
    for (int i = idx0; i < HE * HE; i += stride) {
        int k = i >> 8, n = i & 255;
        g_Wxp16[frag16_idx(k, n, 4)] = __float2half_rn(da1w[n * 768 + 512 + k]);
    }
    for (int i = idx0; i < NG; i += stride) {
        int n = lstm_src_n(i);
        g_benc[0][i] = l1_b[n];
        g_benc[1][i] = l2_b[n];
        g_bdec[i]    = dl_b[n];
    }
}

__global__ void init_kernel() {
    int stride = gridDim.x * blockDim.x;
    int i0 = blockIdx.x * blockDim.x + threadIdx.x;
    __half hz = __float2half_rn(0.f);
    for (int j = i0; j < B * HE; j += stride) {
        g_h16[0][0][j] = hz; g_h16[1][0][j] = hz;
        g_c1[0][j] = 0.f;    g_c2[0][j] = 0.f;
    }
    for (int j = i0; j < B * 512; j += stride) {
        g_dc[0][j] = 0.f;
        g_dc16[0][j] = hz;
    }
}

// ---------------- input attention (a1, a1*a2) — state-independent ---------
__global__ void attn_kernel(const float* __restrict__ X, const float* __restrict__ yprev,
                            const float* __restrict__ e1w, const float* __restrict__ e1b,
                            const float* __restrict__ e2w, const float* __restrict__ e2b) {
    int b = blockIdx.x;
    int j = threadIdx.x;
    float v1 = -1e30f, v2 = -1e30f;
    if (j < D) {
        const float* xb = X + (size_t)b * T * D + j;
        float s1 = 0.f, s2 = 0.f;
#pragma unroll
        for (int t = 0; t < T; ++t) {
            float x = xb[t * D];
            s1 += x * e1w[2 * HE + t];
            s2 += x * e2w[2 * HE + t];
        }
        float yw = 0.f;
#pragma unroll
        for (int t = 0; t < T; ++t) yw += yprev[b * T + t] * e2w[2 * HE + T + t];
        v1 = s1 + e1b[0];
        v2 = s2 + yw + e2b[0];
    }
    __shared__ float red1[128], red2[128];
    red1[j] = v1; red2[j] = v2;
    __syncthreads();
    for (int o = 64; o > 0; o >>= 1) {
        if (j < o) {
            red1[j] = fmaxf(red1[j], red1[j + o]);
            red2[j] = fmaxf(red2[j], red2[j + o]);
        }
        __syncthreads();
    }
    float m1 = red1[0], m2 = red2[0];
    __syncthreads();
    float e1v = (j < D) ? __expf(v1 - m1) : 0.f;
    float e2v = (j < D) ? __expf(v2 - m2) : 0.f;
    red1[j] = e1v; red2[j] = e2v;
    __syncthreads();
    for (int o = 64; o > 0; o >>= 1) {
        if (j < o) { red1[j] += red1[j + o]; red2[j] += red2[j + o]; }
        __syncthreads();
    }
    if (j < D) {
        float a1 = __fdividef(e1v, red1[0]);
        float a2 = __fdividef(e2v, red2[0]);
        g_A1[b * D + j]  = a1;
        g_A12[b * D + j] = a1 * a2;
    }
}

// ---------------- scaled & padded X precompute (fp16) ----------------------
__global__ void prep_xs_kernel(const float* __restrict__ X) {
    int y = blockIdx.y;            // 0..29
    int L = y / T, t = y % T;
    const float* scale = L ? g_A12 : g_A1;
    __half* out = &g_Xs16[L][(size_t)t * B * XP];
    int i = blockIdx.x * blockDim.x + threadIdx.x;   // over B*XP
    if (i >= B * XP) return;
    int b = i / XP, j = i - b * XP;
    float v = 0.f;
    if (j < D) v = scale[b * D + j] * X[((size_t)b * T + t) * D + j];
    out[i] = __float2half_rn(v);
}

// ============= fp16 tensor-core GEMM + fused LSTM epilogue =================
// MODE 0: encoder step (grid.z selects layer); MODE 1: decoder LSTM
template <int MODE>
__global__ __launch_bounds__(256) void lstm_mma_kernel(int t, int pin, int pout) {
    const __half* xsrc = nullptr;
    const __half* h16in = nullptr;
    const float* cin = nullptr;
    __half* h16out = nullptr;
    float* cout = nullptr;
    const __half* Wg;
    const float* bias;
    const float* dcin = nullptr;
    float* dcout = nullptr;
    const __half* d16in = nullptr;
    __half* d16out = nullptr;
    int L = 0;
    int NC;
    if (MODE == 0) {
        L = blockIdx.z;
        xsrc = &g_Xs16[L][(size_t)t * B * XP];
        h16in = g_h16[L][pin];
        h16out = g_h16[L][pout];
        cin = L ? g_c2[pin] : g_c1[pin];
        cout = L ? g_c2[pout] : g_c1[pout];
        Wg = g_Wenc16[L];
        bias = g_benc[L];
        NC = KENC_PAD / BK;      // 22
    } else {
        dcin = g_dc[pin];
        dcout = g_dc[pout];
        d16in = g_dc16[pin];
        d16out = g_dc16[pout];
        Wg = g_Wdec16;
        bias = g_bdec;
        NC = KDEC_PAD / BK;      // 17
    }

    __shared__ __align__(16) unsigned Asw[2][AS32];
    __shared__ __align__(16) unsigned Bsw[2][BS32];

    int tid = threadIdx.x;
    int lane = tid & 31;
    int wid = tid >> 5;
    int wm = wid & 3, wn = wid >> 2;      // 4 row-warps x 2 col-warps
    int lq = lane & 3, lr = lane >> 2;
    int row0 = blockIdx.x * BM;
    int col0 = blockIdx.y * BN;
    int cg = col0 >> 6;

    // A loader: thread = (row, k-half); loads 8 consecutive halves (int4)
    int arow = tid >> 1;
    int akf = tid & 1;
    int agb = row0 + arow;
    int rt = arow & 15, mt = arow >> 4;
    int r = rt & 7, rhalf = rt >> 3;
    int abase = mt * 128 + akf * 2 + rhalf;

    const __half* xrow = (MODE == 0) ? (xsrc + (size_t)agb * XP) : nullptr;
    const __half* hrow = (MODE == 0) ? (h16in + (size_t)agb * HE) : (d16in + (size_t)agb * 512);
    const int2* wp = reinterpret_cast<const int2*>(Wg);

    float acc[2][4][4] = {};
    int4 av;
    int2 bv;

    auto loadChunk = [&](int kc) {
        if (MODE == 0) {
            const __half* p = (kc < 6) ? (xrow + kc * 16 + akf * 8)
                                       : (hrow + (kc - 6) * 16 + akf * 8);
            av = *(const int4*)p;
        } else {
            if (kc < 16) {
                av = *(const int4*)(hrow + kc * 16 + akf * 8);
            } else {
                av = make_int4(0, 0, 0, 0);
                if (akf == 0) av.x = (int)(unsigned)__half_as_ushort(g_yt16[agb]);
            }
        }
        bv = wp[((size_t)(kc * 16 + cg) << 8) + tid];
    };
    auto storeChunk = [&](int buf) {
        unsigned v[4] = {(unsigned)av.x, (unsigned)av.y, (unsigned)av.z, (unsigned)av.w};
        unsigned* as = Asw[buf];
#pragma unroll
        for (int j2 = 0; j2 < 4; ++j2)
            as[abase + (r * 4 + (j2 ^ (r >> 1))) * 4] = v[j2];
        *(int2*)&Bsw[buf][tid * 2] = bv;
    };
    auto compute = [&](int buf) {
        const unsigned* as = Asw[buf];
        const unsigned* bs = Bsw[buf];
        int aoff = (lr * 4 + (lq ^ (lr >> 1))) * 4;
        int4 af[2];
        int2 bf[4];
#pragma unroll
        for (int mi = 0; mi < 2; ++mi)
            af[mi] = *(const int4*)&as[(wm * 2 + mi) * 128 + aoff];
#pragma unroll
        for (int ni = 0; ni < 4; ++ni)
            bf[ni] = *(const int2*)&bs[(wn * 4 + ni) * 64 + lane * 2];
#pragma unroll
        for (int mi = 0; mi < 2; ++mi)
#pragma unroll
            for (int ni = 0; ni < 4; ++ni)
                mma_f16(acc[mi][ni], af[mi], bf[ni]);
    };

    loadChunk(0);
    storeChunk(0);
    __syncthreads();
#pragma unroll 1
    for (int kc = 0; kc < NC; ++kc) {
        int cur = kc & 1;
        if (kc + 1 < NC) loadChunk(kc + 1);
        compute(cur);
        if (kc + 1 < NC) storeChunk(cur ^ 1);
        __syncthreads();
    }

    // ---- fused LSTM epilogue on gate-interleaved columns ----
    int cbase = col0 + wn * 32;
#pragma unroll
    for (int upair = 0; upair < 2; ++upair) {
        int unit = (cbase >> 2) + upair * 4 + lq;
        float bI = bias[cbase + upair * 8 + 2 * lq];
        float bF = bias[cbase + upair * 8 + 2 * lq + 1];
        float bG = bias[cbase + 16 + upair * 8 + 2 * lq];
        float bO = bias[cbase + 16 + upair * 8 + 2 * lq + 1];
#pragma unroll
        for (int mi = 0; mi < 2; ++mi) {
#pragma unroll
            for (int half = 0; half < 2; ++half) {
                int gb = row0 + wm * 32 + mi * 16 + half * 8 + lr;
                float gi = acc[mi][upair][half * 2 + 0] + bI;
                float gf = acc[mi][upair][half * 2 + 1] + bF;
                float gg = acc[mi][2 + upair][half * 2 + 0] + bG;
                float go = acc[mi][2 + upair][half * 2 + 1] + bO;
                float cold = (MODE == 0) ? cin[gb * HE + unit]
                                         : dcin[gb * 512 + 256 + unit];
                float c2 = sigf(gf) * cold + sigf(gi) * ftanh(gg);
                float h2 = sigf(go) * ftanh(c2);
                if (MODE == 0) {
                    h16out[gb * HE + unit] = __float2half_rn(h2);
                    cout[gb * HE + unit] = c2;
                    if (L) {
                        g_Xenc[((size_t)gb * T + t) * HE + unit] = h2;
                        g_Xenc16[((size_t)gb * T + t) * HE + unit] = __float2half_rn(h2);
                    }
                } else {
                    dcout[gb * 512 + unit] = h2;
                    dcout[gb * 512 + 256 + unit] = c2;
                    d16out[gb * 512 + unit] = __float2half_rn(h2);
                    d16out[gb * 512 + 256 + unit] = __float2half_rn(c2);
                }
            }
        }
    }
}

// ---------------- fp16 plain GEMM, N=256 (xenc_proj and q) ----------------
// mode 0: xproj = Xenc @ Wxp + da1b   (M = B*T, K = 256)
// mode 1: q     = [d|c] @ Wq          (M = B,   K = 512)
__global__ __launch_bounds__(256) void gemm256_mma_kernel(int mode, int pin,
                                                          const float* __restrict__ bias) {
    const __half* Aptr;
    const __half* Wptr;
    float* Cptr;
    int lda, NC;
    if (mode == 0) { Aptr = g_Xenc16;     Wptr = g_Wxp16; Cptr = g_xproj; lda = 256; NC = 16; }
    else           { Aptr = g_dc16[pin];  Wptr = g_Wq16;  Cptr = g_q;     lda = 512; NC = 32; }

    __shared__ __align__(16) unsigned Asw[2][AS32];
    __shared__ __align__(16) unsigned Bsw[2][BS32];

    int tid = threadIdx.x;
    int lane = tid & 31;
    int wid = tid >> 5;
    int wm = wid & 3, wn = wid >> 2;
    int lq = lane & 3, lr = lane >> 2;
    int row0 = blockIdx.x * BM;
    int col0 = blockIdx.y * BN;
    int cg = col0 >> 6;

    int arow = tid >> 1;
    int akf = tid & 1;
    int rt = arow & 15, mt = arow >> 4;
    int r = rt & 7, rhalf = rt >> 3;
    int abase = mt * 128 + akf * 2 + rhalf;
    const __half* arowp = Aptr + (size_t)(row0 + arow) * lda + akf * 8;
    const int2* wp = reinterpret_cast<const int2*>(Wptr);

    float acc[2][4][4] = {};
    int4 av;
    int2 bv;

    auto loadChunk = [&](int kc) {
        av = *(const int4*)(arowp + kc * 16);
        bv = wp[((size_t)(kc * 4 + cg) << 8) + tid];
    };
    auto storeChunk = [&](int buf) {
        unsigned v[4] = {(unsigned)av.x, (unsigned)av.y, (unsigned)av.z, (unsigned)av.w};
        unsigned* as = Asw[buf];
#pragma unroll
        for (int j2 = 0; j2 < 4; ++j2)
            as[abase + (r * 4 + (j2 ^ (r >> 1))) * 4] = v[j2];
        *(int2*)&Bsw[buf][tid * 2] = bv;
    };
    auto compute = [&](int buf) {
        const unsigned* as = Asw[buf];
        const unsigned* bs = Bsw[buf];
        int aoff = (lr * 4 + (lq ^ (lr >> 1))) * 4;
        int4 af[2];
        int2 bf[4];
#pragma unroll
        for (int mi = 0; mi < 2; ++mi)
            af[mi] = *(const int4*)&as[(wm * 2 + mi) * 128 + aoff];
#pragma unroll
        for (int ni = 0; ni < 4; ++ni)
            bf[ni] = *(const int2*)&bs[(wn * 4 + ni) * 64 + lane * 2];
#pragma unroll
        for (int mi = 0; mi < 2; ++mi)
#pragma unroll
            for (int ni = 0; ni < 4; ++ni)
                mma_f16(acc[mi][ni], af[mi], bf[ni]);
    };

    loadChunk(0);
    storeChunk(0);
    __syncthreads();
#pragma unroll 1
    for (int kc = 0; kc < NC; ++kc) {
        int cur = kc & 1;
        if (kc + 1 < NC) loadChunk(kc + 1);
        compute(cur);
        if (kc + 1 < NC) storeChunk(cur ^ 1);
        __syncthreads();
    }

#pragma unroll
    for (int mi = 0; mi < 2; ++mi) {
#pragma unroll
        for (int half = 0; half < 2; ++half) {
            int gb = row0 + wm * 32 + mi * 16 + half * 8 + lr;
#pragma unroll
            for (int ni = 0; ni < 4; ++ni) {
                int col = col0 + wn * 32 + ni * 8 + 2 * lq;
                float v0 = acc[mi][ni][half * 2 + 0] + (bias ? bias[col] : 0.f);
                float v1 = acc[mi][ni][half * 2 + 1] + (bias ? bias[col + 1] : 0.f);
                *(float2*)&Cptr[(size_t)gb * HE + col] = make_float2(v0, v1);
            }
        }
    }
}

// ---------------- decoder attention (row-wise fused) ----------------------
__global__ __launch_bounds__(256) void dec_attn_kernel(const float* __restrict__ yprev,
                                                       const float* __restrict__ a2w,
                                                       const float* __restrict__ a2b,
                                                       const float* __restrict__ fcw,
                                                       const float* __restrict__ fcb, int t) {
    int b = blockIdx.x;
    int h = threadIdx.x;
    float qh = g_q[b * HE + h];
    float w = a2w[h];
    const float* xp = g_xproj + (size_t)(b * T) * HE + h;
    float sloc[T];
#pragma unroll
    for (int tt = 0; tt < T; ++tt) sloc[tt] = ftanh(xp[tt * HE] + qh) * w;

    __shared__ float part[8][T];
    __shared__ float beta[T];
    int lane = h & 31, wid = h >> 5;
#pragma unroll
    for (int tt = 0; tt < T; ++tt) {
        float v = sloc[tt];
        for (int o = 16; o > 0; o >>= 1) v += __shfl_down_sync(0xFFFFFFFFu, v, o);
        if (!lane) part[wid][tt] = v;
    }
    __syncthreads();
    if (h == 0) {
        float sc[T];
        float mx = -1e30f;
#pragma unroll
        for (int tt = 0; tt < T; ++tt) {
            float s = a2b[0];
#pragma unroll
            for (int w8 = 0; w8 < 8; ++w8) s += part[w8][tt];
            sc[tt] = s;
            mx = fmaxf(mx, s);
        }
        float sum = 0.f;
#pragma unroll
        for (int tt = 0; tt < T; ++tt) { sc[tt] = __expf(sc[tt] - mx); sum += sc[tt]; }
        float inv = __fdividef(1.f, sum);
#pragma unroll
        for (int tt = 0; tt < T; ++tt) beta[tt] = sc[tt] * inv;
    }
    __syncthreads();
    const float* xe = g_Xenc + (size_t)(b * T) * HE + h;
    float ctx = 0.f;
#pragma unroll
    for (int tt = 0; tt < T; ++tt) ctx += beta[tt] * xe[tt * HE];
    g_ctx[b * HE + h] = ctx;
    float yv = ctx * fcw[h];
    for (int o = 16; o > 0; o >>= 1) yv += __shfl_down_sync(0xFFFFFFFFu, yv, o);
    __syncthreads();
    if (!lane) part[wid][0] = yv;
    __syncthreads();
    if (h == 0) {
        float s = 0.f;
#pragma unroll
        for (int w8 = 0; w8 < 8; ++w8) s += part[w8][0];
        g_yt16[b] = __float2half_rn(s + yprev[b * T + t] * fcw[HE] + fcb[0]);
    }
}

// ---------------- final output --------------------------------------------
__global__ void final_kernel(const float* __restrict__ ffw, const float* __restrict__ ffb,
                             float* __restrict__ out, int pin) {
    int gtid = blockIdx.x * blockDim.x + threadIdx.x;
    int warp = gtid >> 5;
    int lane = gtid & 31;
    if (warp >= B) return;
    const float* d = g_dc[pin] + warp * 512;
    const float* ctx = g_ctx + warp * HE;
    float s = 0.f;
    for (int h = lane; h < HE; h += 32) s += d[h] * ffw[h] + ctx[h] * ffw[HE + h];
    for (int o = 16; o > 0; o >>= 1) s += __shfl_down_sync(0xFFFFFFFFu, s, o);
    if (!lane) out[warp] = s + ffb[0];
}

// ---------------- launch ---------------------------------------------------
extern "C" void kernel_launch(void* const* d_in, const int* in_sizes, int n_in,
                              void* d_out, int out_size) {
    const float* X      = (const float*)d_in[0];
    const float* yprev  = (const float*)d_in[1];
    const float* e1w    = (const float*)d_in[2];
    const float* e1b    = (const float*)d_in[3];
    const float* e2w    = (const float*)d_in[4];
    const float* e2b    = (const float*)d_in[5];
    const float* l1_wih = (const float*)d_in[6];
    const float* l1_whh = (const float*)d_in[7];
    const float* l1_b   = (const float*)d_in[8];
    const float* l2_wih = (const float*)d_in[9];
    const float* l2_whh = (const float*)d_in[10];
    const float* l2_b   = (const float*)d_in[11];
    const float* da1w   = (const float*)d_in[12];
    const float* da1b   = (const float*)d_in[13];
    const float* da2w   = (const float*)d_in[14];
    const float* da2b   = (const float*)d_in[15];
    const float* dlwih  = (const float*)d_in[16];
    const float* dlwhh  = (const float*)d_in[17];
    const float* dlb    = (const float*)d_in[18];
    const float* fcw    = (const float*)d_in[19];
    const float* fcb    = (const float*)d_in[20];
    const float* ffw    = (const float*)d_in[21];
    const float* ffb    = (const float*)d_in[22];
    float* out = (float*)d_out;

    pack_kernel<<<512, 256>>>(l1_wih, l1_whh, l1_b, l2_wih, l2_whh, l2_b,
                              dlwih, dlwhh, dlb, da1w);
    init_kernel<<<512, 256>>>();
    attn_kernel<<<B, 128>>>(X, yprev, e1w, e1b, e2w, e2b);
    prep_xs_kernel<<<dim3((B * XP + 255) / 256, 2 * T), 256>>>(X);

    for (int t = 0; t < T; ++t)
        lstm_mma_kernel<0><<<dim3(B / BM, NG / BN, 2), 256>>>(t, t & 1, (t + 1) & 1);

    // xenc_proj over all (b, t)
    gemm256_mma_kernel<<<dim3(B * T / BM, HE / BN), 256>>>(0, 0, da1b);

    for (int t = 0; t < T; ++t) {
        gemm256_mma_kernel<<<dim3(B / BM, HE / BN), 256>>>(1, t & 1, nullptr);
        dec_attn_kernel<<<B, 256>>>(yprev, da2w, da2b, fcw, fcb, t);
        lstm_mma_kernel<1><<<dim3(B / BM, NG / BN), 256>>>(0, t & 1, (t + 1) & 1);
    }

    final_kernel<<<B * 32 / 256, 256>>>(ffw, ffb, out, T & 1);
}

// round 14
// speedup vs baseline: 4.0594x; 1.2171x over previous
#include <cuda_runtime.h>
#include <cuda_fp16.h>

#define B 8192
#define T 15
#define D 81
#define HE 256
#define NG 1024
#define XP 96         // padded x-width for encoder
#define KENC_PAD 352  // 96 (x, padded) + 256 (h)
#define KDEC_PAD 272  // 256 (d) + 16 (y + pad)

#define BM 128
#define BN 64
#define BK 16
#define AS32 1040     // per-buffer A words: 8 mt * 128 + 16 pad
#define BS32 528      // per-buffer B words: 512 + 16 pad

// ---------------- scratch (static device memory; no allocations) ----------
__device__ float  g_A12[B * D];
__device__ __half g_Xs16[T * B * XP];           // [t][b][96] a1*a2-scaled, padded, fp16
__device__ __half g_Wenc16[KENC_PAD * NG];      // fragment-packed fp16 (layer-2 only)
__device__ float  g_benc[NG];
__device__ __half g_Wdec16[KDEC_PAD * NG];
__device__ float  g_bdec[NG];
__device__ __half g_Wq16[512 * HE];             // k<256 -> W1d, else W1c
__device__ __half g_Wxp16[HE * HE];             // [k][n] = W1x[n][k]
__device__ __half g_h16[2][B * HE];             // [parity] encoder (layer-2) h fp16
__device__ float  g_c2[2][B * HE];
__device__ float  g_Xenc[B * T * HE];           // fp32 (decoder attention ctx)
__device__ __half g_Xenc16[B * T * HE];         // fp16 (xproj GEMM A)
__device__ float  g_xproj[B * T * HE];
__device__ float  g_dc[2][B * 512];             // decoder state [d | c] fp32
__device__ __half g_dc16[2][B * 512];           // fp16 copy for GEMM A
__device__ float  g_q[B * HE];
__device__ __half g_yt16[B];
__device__ float  g_ctx[B * HE];

// ---------------- math helpers -------------------------------------------
__device__ __forceinline__ float sigf(float x) {
    return __fdividef(1.f, 1.f + __expf(-x));
}
__device__ __forceinline__ float ftanh(float x) {
    float e = __expf(-2.f * fabsf(x));
    float r = __fdividef(1.f - e, 1.f + e);
    return copysignf(r, x);
}
__device__ __forceinline__ void mma_f16(float* c, const int4& a, const int2& b) {
    asm volatile(
        "mma.sync.aligned.m16n8k16.row.col.f32.f16.f16.f32 "
        "{%0,%1,%2,%3}, {%4,%5,%6,%7}, {%8,%9}, {%0,%1,%2,%3};\n"
        : "+f"(c[0]), "+f"(c[1]), "+f"(c[2]), "+f"(c[3])
        : "r"(a.x), "r"(a.y), "r"(a.z), "r"(a.w), "r"(b.x), "r"(b.y));
}

// Fragment-packed fp16 B-weight index for m16n8k16.
__device__ __forceinline__ size_t frag16_idx(int k, int c, int ncg) {
    int block = (k >> 4) * ncg + (c >> 6);
    int nt = (c & 63) >> 3;
    int lane = ((c & 7) << 2) + ((k >> 1) & 3);
    int khalf = (k >> 3) & 1, p = k & 1;
    return (size_t)block * 1024 + nt * 128 + lane * 4 + khalf * 2 + p;
}

// Packed column mapping for LSTM weights (col -> original row n)
__device__ __forceinline__ int lstm_src_n(int c) {
    int g32 = c >> 5, p = c & 31;
    int u = (g32 << 3) + ((p & 15) >> 1);
    int gate = ((p & 16) ? 2 : 0) + (p & 1);
    return gate * HE + u;
}

// ---------------- weight packing ------------------------------------------
__global__ void pack_kernel(const float* __restrict__ l2_wih, const float* __restrict__ l2_whh,
                            const float* __restrict__ l2_b,
                            const float* __restrict__ dl_wih, const float* __restrict__ dl_whh,
                            const float* __restrict__ dl_b,
                            const float* __restrict__ da1w) {
    int stride = gridDim.x * blockDim.x;
    int idx0 = blockIdx.x * blockDim.x + threadIdx.x;
    // Encoder (layer 2 only): k order = [x 0..95 (81 real) | h 0..255]
    for (int i = idx0; i < KENC_PAD * NG; i += stride) {
        int k = i >> 10, col = i & 1023;
        int n = lstm_src_n(col);
        float v = 0.f;
        if (k < D)        v = l2_wih[n * D + k];
        else if (k >= XP) v = l2_whh[n * HE + (k - XP)];
        g_Wenc16[frag16_idx(k, col, 16)] = __float2half_rn(v);
    }
    // Decoder: k order = [d 0..255 | y at 256 | pad]
    for (int i = idx0; i < KDEC_PAD * NG; i += stride) {
        int k = i >> 10, col = i & 1023;
        int n = lstm_src_n(col);
        float v = 0.f;
        if (k < 256)       v = dl_whh[n * HE + k];
        else if (k == 256) v = dl_wih[n];
        g_Wdec16[frag16_idx(k, col, 16)] = __float2half_rn(v);
    }
    for (int i = idx0; i < 512 * HE; i += stride) {
        int k = i >> 8, n = i & 255;
        float v = (k < HE) ? da1w[n * 768 + k] : da1w[n * 768 + 256 + (k - HE)];
        g_Wq16[frag16_idx(k, n, 4)] = __float2half_rn(v);
    }
    for (int i = idx0; i < HE * HE; i += stride) {
        int k = i >> 8, n = i & 255;
        g_Wxp16[frag16_idx(k, n, 4)] = __float2half_rn(da1w[n * 768 + 512 + k]);
    }
    for (int i = idx0; i < NG; i += stride) {
        int n = lstm_src_n(i);
        g_benc[i] = l2_b[n];
        g_bdec[i] = dl_b[n];
    }
}

__global__ void init_kernel() {
    int stride = gridDim.x * blockDim.x;
    int i0 = blockIdx.x * blockDim.x + threadIdx.x;
    __half hz = __float2half_rn(0.f);
    for (int j = i0; j < B * HE; j += stride) {
        g_h16[0][j] = hz;
        g_c2[0][j] = 0.f;
    }
    for (int j = i0; j < B * 512; j += stride) {
        g_dc[0][j] = 0.f;
        g_dc16[0][j] = hz;
    }
}

// ---------------- input attention (a1*a2) — state-independent -------------
__global__ void attn_kernel(const float* __restrict__ X, const float* __restrict__ yprev,
                            const float* __restrict__ e1w, const float* __restrict__ e1b,
                            const float* __restrict__ e2w, const float* __restrict__ e2b) {
    int b = blockIdx.x;
    int j = threadIdx.x;
    float v1 = -1e30f, v2 = -1e30f;
    if (j < D) {
        const float* xb = X + (size_t)b * T * D + j;
        float s1 = 0.f, s2 = 0.f;
#pragma unroll
        for (int t = 0; t < T; ++t) {
            float x = xb[t * D];
            s1 += x * e1w[2 * HE + t];
            s2 += x * e2w[2 * HE + t];
        }
        float yw = 0.f;
#pragma unroll
        for (int t = 0; t < T; ++t) yw += yprev[b * T + t] * e2w[2 * HE + T + t];
        v1 = s1 + e1b[0];
        v2 = s2 + yw + e2b[0];
    }
    __shared__ float red1[128], red2[128];
    red1[j] = v1; red2[j] = v2;
    __syncthreads();
    for (int o = 64; o > 0; o >>= 1) {
        if (j < o) {
            red1[j] = fmaxf(red1[j], red1[j + o]);
            red2[j] = fmaxf(red2[j], red2[j + o]);
        }
        __syncthreads();
    }
    float m1 = red1[0], m2 = red2[0];
    __syncthreads();
    float e1v = (j < D) ? __expf(v1 - m1) : 0.f;
    float e2v = (j < D) ? __expf(v2 - m2) : 0.f;
    red1[j] = e1v; red2[j] = e2v;
    __syncthreads();
    for (int o = 64; o > 0; o >>= 1) {
        if (j < o) { red1[j] += red1[j + o]; red2[j] += red2[j + o]; }
        __syncthreads();
    }
    if (j < D) {
        float a1 = __fdividef(e1v, red1[0]);
        float a2 = __fdividef(e2v, red2[0]);
        g_A12[b * D + j] = a1 * a2;
    }
}

// ---------------- scaled & padded X precompute (fp16, layer-2 scale) -------
__global__ void prep_xs_kernel(const float* __restrict__ X) {
    int t = blockIdx.y;
    __half* out = &g_Xs16[(size_t)t * B * XP];
    int i = blockIdx.x * blockDim.x + threadIdx.x;   // over B*XP
    if (i >= B * XP) return;
    int b = i / XP, j = i - b * XP;
    float v = 0.f;
    if (j < D) v = g_A12[b * D + j] * X[((size_t)b * T + t) * D + j];
    out[i] = __float2half_rn(v);
}

// ============= fp16 tensor-core GEMM + fused LSTM epilogue =================
// MODE 0: encoder step (layer 2 only); MODE 1: decoder LSTM
template <int MODE>
__global__ __launch_bounds__(256) void lstm_mma_kernel(int t, int pin, int pout) {
    const __half* xsrc = nullptr;
    const __half* h16in = nullptr;
    const float* cin = nullptr;
    __half* h16out = nullptr;
    float* cout = nullptr;
    const __half* Wg;
    const float* bias;
    const float* dcin = nullptr;
    float* dcout = nullptr;
    const __half* d16in = nullptr;
    __half* d16out = nullptr;
    int NC;
    if (MODE == 0) {
        xsrc = &g_Xs16[(size_t)t * B * XP];
        h16in = g_h16[pin];
        h16out = g_h16[pout];
        cin = g_c2[pin];
        cout = g_c2[pout];
        Wg = g_Wenc16;
        bias = g_benc;
        NC = KENC_PAD / BK;      // 22
    } else {
        dcin = g_dc[pin];
        dcout = g_dc[pout];
        d16in = g_dc16[pin];
        d16out = g_dc16[pout];
        Wg = g_Wdec16;
        bias = g_bdec;
        NC = KDEC_PAD / BK;      // 17
    }

    __shared__ __align__(16) unsigned Asw[2][AS32];
    __shared__ __align__(16) unsigned Bsw[2][BS32];

    int tid = threadIdx.x;
    int lane = tid & 31;
    int wid = tid >> 5;
    int wm = wid & 3, wn = wid >> 2;      // 4 row-warps x 2 col-warps
    int lq = lane & 3, lr = lane >> 2;
    int row0 = blockIdx.x * BM;
    int col0 = blockIdx.y * BN;
    int cg = col0 >> 6;

    // A loader: thread = (row, k-half); loads 8 consecutive halves (int4)
    int arow = tid >> 1;
    int akf = tid & 1;
    int agb = row0 + arow;
    int rt = arow & 15, mt = arow >> 4;
    int r = rt & 7, rhalf = rt >> 3;
    int abase = mt * 128 + akf * 2 + rhalf;

    const __half* xrow = (MODE == 0) ? (xsrc + (size_t)agb * XP) : nullptr;
    const __half* hrow = (MODE == 0) ? (h16in + (size_t)agb * HE) : (d16in + (size_t)agb * 512);
    const int2* wp = reinterpret_cast<const int2*>(Wg);

    float acc[2][4][4] = {};
    int4 av;
    int2 bv;

    auto loadChunk = [&](int kc) {
        if (MODE == 0) {
            const __half* p = (kc < 6) ? (xrow + kc * 16 + akf * 8)
                                       : (hrow + (kc - 6) * 16 + akf * 8);
            av = *(const int4*)p;
        } else {
            if (kc < 16) {
                av = *(const int4*)(hrow + kc * 16 + akf * 8);
            } else {
                av = make_int4(0, 0, 0, 0);
                if (akf == 0) av.x = (int)(unsigned)__half_as_ushort(g_yt16[agb]);
            }
        }
        bv = wp[((size_t)(kc * 16 + cg) << 8) + tid];
    };
    auto storeChunk = [&](int buf) {
        unsigned v[4] = {(unsigned)av.x, (unsigned)av.y, (unsigned)av.z, (unsigned)av.w};
        unsigned* as = Asw[buf];
#pragma unroll
        for (int j2 = 0; j2 < 4; ++j2)
            as[abase + (r * 4 + (j2 ^ (r >> 1))) * 4] = v[j2];
        *(int2*)&Bsw[buf][tid * 2] = bv;
    };
    auto compute = [&](int buf) {
        const unsigned* as = Asw[buf];
        const unsigned* bs = Bsw[buf];
        int aoff = (lr * 4 + (lq ^ (lr >> 1))) * 4;
        int4 af[2];
        int2 bf[4];
#pragma unroll
        for (int mi = 0; mi < 2; ++mi)
            af[mi] = *(const int4*)&as[(wm * 2 + mi) * 128 + aoff];
#pragma unroll
        for (int ni = 0; ni < 4; ++ni)
            bf[ni] = *(const int2*)&bs[(wn * 4 + ni) * 64 + lane * 2];
#pragma unroll
        for (int mi = 0; mi < 2; ++mi)
#pragma unroll
            for (int ni = 0; ni < 4; ++ni)
                mma_f16(acc[mi][ni], af[mi], bf[ni]);
    };

    loadChunk(0);
    storeChunk(0);
    __syncthreads();
#pragma unroll 1
    for (int kc = 0; kc < NC; ++kc) {
        int cur = kc & 1;
        if (kc + 1 < NC) loadChunk(kc + 1);
        compute(cur);
        if (kc + 1 < NC) storeChunk(cur ^ 1);
        __syncthreads();
    }

    // ---- fused LSTM epilogue on gate-interleaved columns ----
    int cbase = col0 + wn * 32;
#pragma unroll
    for (int upair = 0; upair < 2; ++upair) {
        int unit = (cbase >> 2) + upair * 4 + lq;
        float bI = bias[cbase + upair * 8 + 2 * lq];
        float bF = bias[cbase + upair * 8 + 2 * lq + 1];
        float bG = bias[cbase + 16 + upair * 8 + 2 * lq];
        float bO = bias[cbase + 16 + upair * 8 + 2 * lq + 1];
#pragma unroll
        for (int mi = 0; mi < 2; ++mi) {
#pragma unroll
            for (int half = 0; half < 2; ++half) {
                int gb = row0 + wm * 32 + mi * 16 + half * 8 + lr;
                float gi = acc[mi][upair][half * 2 + 0] + bI;
                float gf = acc[mi][upair][half * 2 + 1] + bF;
                float gg = acc[mi][2 + upair][half * 2 + 0] + bG;
                float go = acc[mi][2 + upair][half * 2 + 1] + bO;
                float cold = (MODE == 0) ? cin[gb * HE + unit]
                                         : dcin[gb * 512 + 256 + unit];
                float c2 = sigf(gf) * cold + sigf(gi) * ftanh(gg);
                float h2 = sigf(go) * ftanh(c2);
                if (MODE == 0) {
                    h16out[gb * HE + unit] = __float2half_rn(h2);
                    cout[gb * HE + unit] = c2;
                    g_Xenc[((size_t)gb * T + t) * HE + unit] = h2;
                    g_Xenc16[((size_t)gb * T + t) * HE + unit] = __float2half_rn(h2);
                } else {
                    dcout[gb * 512 + unit] = h2;
                    dcout[gb * 512 + 256 + unit] = c2;
                    d16out[gb * 512 + unit] = __float2half_rn(h2);
                    d16out[gb * 512 + 256 + unit] = __float2half_rn(c2);
                }
            }
        }
    }
}

// ---------------- fp16 plain GEMM, N=256 (xenc_proj and q) ----------------
// mode 0: xproj = Xenc @ Wxp + da1b   (M = B*T, K = 256)
// mode 1: q     = [d|c] @ Wq          (M = B,   K = 512)
__global__ __launch_bounds__(256) void gemm256_mma_kernel(int mode, int pin,
                                                          const float* __restrict__ bias) {
    const __half* Aptr;
    const __half* Wptr;
    float* Cptr;
    int lda, NC;
    if (mode == 0) { Aptr = g_Xenc16;     Wptr = g_Wxp16; Cptr = g_xproj; lda = 256; NC = 16; }
    else           { Aptr = g_dc16[pin];  Wptr = g_Wq16;  Cptr = g_q;     lda = 512; NC = 32; }

    __shared__ __align__(16) unsigned Asw[2][AS32];
    __shared__ __align__(16) unsigned Bsw[2][BS32];

    int tid = threadIdx.x;
    int lane = tid & 31;
    int wid = tid >> 5;
    int wm = wid & 3, wn = wid >> 2;
    int lq = lane & 3, lr = lane >> 2;
    int row0 = blockIdx.x * BM;
    int col0 = blockIdx.y * BN;
    int cg = col0 >> 6;

    int arow = tid >> 1;
    int akf = tid & 1;
    int rt = arow & 15, mt = arow >> 4;
    int r = rt & 7, rhalf = rt >> 3;
    int abase = mt * 128 + akf * 2 + rhalf;
    const __half* arowp = Aptr + (size_t)(row0 + arow) * lda + akf * 8;
    const int2* wp = reinterpret_cast<const int2*>(Wptr);

    float acc[2][4][4] = {};
    int4 av;
    int2 bv;

    auto loadChunk = [&](int kc) {
        av = *(const int4*)(arowp + kc * 16);
        bv = wp[((size_t)(kc * 4 + cg) << 8) + tid];
    };
    auto storeChunk = [&](int buf) {
        unsigned v[4] = {(unsigned)av.x, (unsigned)av.y, (unsigned)av.z, (unsigned)av.w};
        unsigned* as = Asw[buf];
#pragma unroll
        for (int j2 = 0; j2 < 4; ++j2)
            as[abase + (r * 4 + (j2 ^ (r >> 1))) * 4] = v[j2];
        *(int2*)&Bsw[buf][tid * 2] = bv;
    };
    auto compute = [&](int buf) {
        const unsigned* as = Asw[buf];
        const unsigned* bs = Bsw[buf];
        int aoff = (lr * 4 + (lq ^ (lr >> 1))) * 4;
        int4 af[2];
        int2 bf[4];
#pragma unroll
        for (int mi = 0; mi < 2; ++mi)
            af[mi] = *(const int4*)&as[(wm * 2 + mi) * 128 + aoff];
#pragma unroll
        for (int ni = 0; ni < 4; ++ni)
            bf[ni] = *(const int2*)&bs[(wn * 4 + ni) * 64 + lane * 2];
#pragma unroll
        for (int mi = 0; mi < 2; ++mi)
#pragma unroll
            for (int ni = 0; ni < 4; ++ni)
                mma_f16(acc[mi][ni], af[mi], bf[ni]);
    };

    loadChunk(0);
    storeChunk(0);
    __syncthreads();
#pragma unroll 1
    for (int kc = 0; kc < NC; ++kc) {
        int cur = kc & 1;
        if (kc + 1 < NC) loadChunk(kc + 1);
        compute(cur);
        if (kc + 1 < NC) storeChunk(cur ^ 1);
        __syncthreads();
    }

#pragma unroll
    for (int mi = 0; mi < 2; ++mi) {
#pragma unroll
        for (int half = 0; half < 2; ++half) {
            int gb = row0 + wm * 32 + mi * 16 + half * 8 + lr;
#pragma unroll
            for (int ni = 0; ni < 4; ++ni) {
                int col = col0 + wn * 32 + ni * 8 + 2 * lq;
                float v0 = acc[mi][ni][half * 2 + 0] + (bias ? bias[col] : 0.f);
                float v1 = acc[mi][ni][half * 2 + 1] + (bias ? bias[col + 1] : 0.f);
                *(float2*)&Cptr[(size_t)gb * HE + col] = make_float2(v0, v1);
            }
        }
    }
}

// ---------------- decoder attention (row-wise fused) ----------------------
__global__ __launch_bounds__(256) void dec_attn_kernel(const float* __restrict__ yprev,
                                                       const float* __restrict__ a2w,
                                                       const float* __restrict__ a2b,
                                                       const float* __restrict__ fcw,
                                                       const float* __restrict__ fcb, int t) {
    int b = blockIdx.x;
    int h = threadIdx.x;
    float qh = g_q[b * HE + h];
    float w = a2w[h];
    const float* xp = g_xproj + (size_t)(b * T) * HE + h;
    float sloc[T];
#pragma unroll
    for (int tt = 0; tt < T; ++tt) sloc[tt] = ftanh(xp[tt * HE] + qh) * w;

    __shared__ float part[8][T];
    __shared__ float beta[T];
    int lane = h & 31, wid = h >> 5;
#pragma unroll
    for (int tt = 0; tt < T; ++tt) {
        float v = sloc[tt];
        for (int o = 16; o > 0; o >>= 1) v += __shfl_down_sync(0xFFFFFFFFu, v, o);
        if (!lane) part[wid][tt] = v;
    }
    __syncthreads();
    if (h == 0) {
        float sc[T];
        float mx = -1e30f;
#pragma unroll
        for (int tt = 0; tt < T; ++tt) {
            float s = a2b[0];
#pragma unroll
            for (int w8 = 0; w8 < 8; ++w8) s += part[w8][tt];
            sc[tt] = s;
            mx = fmaxf(mx, s);
        }
        float sum = 0.f;
#pragma unroll
        for (int tt = 0; tt < T; ++tt) { sc[tt] = __expf(sc[tt] - mx); sum += sc[tt]; }
        float inv = __fdividef(1.f, sum);
#pragma unroll
        for (int tt = 0; tt < T; ++tt) beta[tt] = sc[tt] * inv;
    }
    __syncthreads();
    const float* xe = g_Xenc + (size_t)(b * T) * HE + h;
    float ctx = 0.f;
#pragma unroll
    for (int tt = 0; tt < T; ++tt) ctx += beta[tt] * xe[tt * HE];
    g_ctx[b * HE + h] = ctx;
    float yv = ctx * fcw[h];
    for (int o = 16; o > 0; o >>= 1) yv += __shfl_down_sync(0xFFFFFFFFu, yv, o);
    __syncthreads();
    if (!lane) part[wid][0] = yv;
    __syncthreads();
    if (h == 0) {
        float s = 0.f;
#pragma unroll
        for (int w8 = 0; w8 < 8; ++w8) s += part[w8][0];
        g_yt16[b] = __float2half_rn(s + yprev[b * T + t] * fcw[HE] + fcb[0]);
    }
}

// ---------------- final output --------------------------------------------
__global__ void final_kernel(const float* __restrict__ ffw, const float* __restrict__ ffb,
                             float* __restrict__ out, int pin) {
    int gtid = blockIdx.x * blockDim.x + threadIdx.x;
    int warp = gtid >> 5;
    int lane = gtid & 31;
    if (warp >= B) return;
    const float* d = g_dc[pin] + warp * 512;
    const float* ctx = g_ctx + warp * HE;
    float s = 0.f;
    for (int h = lane; h < HE; h += 32) s += d[h] * ffw[h] + ctx[h] * ffw[HE + h];
    for (int o = 16; o > 0; o >>= 1) s += __shfl_down_sync(0xFFFFFFFFu, s, o);
    if (!lane) out[warp] = s + ffb[0];
}

// ---------------- launch ---------------------------------------------------
extern "C" void kernel_launch(void* const* d_in, const int* in_sizes, int n_in,
                              void* d_out, int out_size) {
    const float* X      = (const float*)d_in[0];
    const float* yprev  = (const float*)d_in[1];
    const float* e1w    = (const float*)d_in[2];
    const float* e1b    = (const float*)d_in[3];
    const float* e2w    = (const float*)d_in[4];
    const float* e2b    = (const float*)d_in[5];
    const float* l2_wih = (const float*)d_in[9];
    const float* l2_whh = (const float*)d_in[10];
    const float* l2_b   = (const float*)d_in[11];
    const float* da1w   = (const float*)d_in[12];
    const float* da1b   = (const float*)d_in[13];
    const float* da2w   = (const float*)d_in[14];
    const float* da2b   = (const float*)d_in[15];
    const float* dlwih  = (const float*)d_in[16];
    const float* dlwhh  = (const float*)d_in[17];
    const float* dlb    = (const float*)d_in[18];
    const float* fcw    = (const float*)d_in[19];
    const float* fcb    = (const float*)d_in[20];
    const float* ffw    = (const float*)d_in[21];
    const float* ffb    = (const float*)d_in[22];
    float* out = (float*)d_out;

    pack_kernel<<<512, 256>>>(l2_wih, l2_whh, l2_b, dlwih, dlwhh, dlb, da1w);
    init_kernel<<<512, 256>>>();
    attn_kernel<<<B, 128>>>(X, yprev, e1w, e1b, e2w, e2b);
    prep_xs_kernel<<<dim3((B * XP + 255) / 256, T), 256>>>(X);

    for (int t = 0; t < T; ++t)
        lstm_mma_kernel<0><<<dim3(B / BM, NG / BN), 256>>>(t, t & 1, (t + 1) & 1);

    // xenc_proj over all (b, t)
    gemm256_mma_kernel<<<dim3(B * T / BM, HE / BN), 256>>>(0, 0, da1b);

    for (int t = 0; t < T; ++t) {
        gemm256_mma_kernel<<<dim3(B / BM, HE / BN), 256>>>(1, t & 1, nullptr);
        dec_attn_kernel<<<B, 256>>>(yprev, da2w, da2b, fcw, fcb, t);
        lstm_mma_kernel<1><<<dim3(B / BM, NG / BN), 256>>>(0, t & 1, (t + 1) & 1);
    }

    final_kernel<<<B * 32 / 256, 256>>>(ffw, ffb, out, T & 1);
}

// round 15
// speedup vs baseline: 4.4749x; 1.1024x over previous
#include <cuda_runtime.h>
#include <cuda_fp16.h>

#define B 8192
#define T 15
#define D 81
#define HE 256
#define NG 1024
#define XP 96         // padded x-width for encoder
#define KENC_PAD 352  // 96 (x, padded) + 256 (h)
#define KDEC_PAD 256  // 256 (d); y handled in epilogue

#define BM 128
#define BN 128
#define BK 16
#define AS32 1040     // per-buffer A words: 8 mt * 128 + 16 pad
#define BS32 1040     // per-buffer B words: 1024 + 16 pad

// ---------------- scratch (static device memory; no allocations) ----------
__device__ __half g_Xs16[T * B * XP];           // [t][b][96] a1*a2-scaled, padded, fp16
__device__ __half g_Wenc16[KENC_PAD * NG];      // fragment-packed fp16 (layer-2 only)
__device__ float  g_benc[NG];
__device__ __half g_Wdec16[KDEC_PAD * NG];
__device__ float  g_bdec[NG];
__device__ float  g_wyt[NG];                    // packed dl_wih (y contribution)
__device__ __half g_Wq16[512 * HE];             // k<256 -> W1d, else W1c
__device__ __half g_Wxp16[HE * HE];             // [k][n] = W1x[n][k]
__device__ __half g_h16[2][B * HE];             // [parity] encoder (layer-2) h fp16
__device__ float  g_c2[2][B * HE];
__device__ __half g_Xenc16[B * T * HE];         // fp16 (xproj GEMM A + attention ctx)
__device__ __half g_xproj16[B * T * HE];
__device__ float  g_dc[2][B * 512];             // decoder state [d | c] fp32
__device__ __half g_dc16[2][B * 512];           // fp16 copy for GEMM A
__device__ float  g_q[B * HE];
__device__ __half g_yt16[B];
__device__ float  g_ctx[B * HE];

// ---------------- math helpers -------------------------------------------
__device__ __forceinline__ float sigf(float x) {
    return __fdividef(1.f, 1.f + __expf(-x));
}
__device__ __forceinline__ float ftanh(float x) {
    float e = __expf(-2.f * fabsf(x));
    float r = __fdividef(1.f - e, 1.f + e);
    return copysignf(r, x);
}
__device__ __forceinline__ void mma_f16(float* c, const int4& a, const int2& b) {
    asm volatile(
        "mma.sync.aligned.m16n8k16.row.col.f32.f16.f16.f32 "
        "{%0,%1,%2,%3}, {%4,%5,%6,%7}, {%8,%9}, {%0,%1,%2,%3};\n"
        : "+f"(c[0]), "+f"(c[1]), "+f"(c[2]), "+f"(c[3])
        : "r"(a.x), "r"(a.y), "r"(a.z), "r"(a.w), "r"(b.x), "r"(b.y));
}

// Fragment-packed fp16 B-weight index for m16n8k16.
__device__ __forceinline__ size_t frag16_idx(int k, int c, int ncg) {
    int block = (k >> 4) * ncg + (c >> 6);
    int nt = (c & 63) >> 3;
    int lane = ((c & 7) << 2) + ((k >> 1) & 3);
    int khalf = (k >> 3) & 1, p = k & 1;
    return (size_t)block * 1024 + nt * 128 + lane * 4 + khalf * 2 + p;
}

// Packed column mapping for LSTM weights (col -> original row n)
__device__ __forceinline__ int lstm_src_n(int c) {
    int g32 = c >> 5, p = c & 31;
    int u = (g32 << 3) + ((p & 15) >> 1);
    int gate = ((p & 16) ? 2 : 0) + (p & 1);
    return gate * HE + u;
}

// ---------------- weight packing ------------------------------------------
__global__ void pack_kernel(const float* __restrict__ l2_wih, const float* __restrict__ l2_whh,
                            const float* __restrict__ l2_b,
                            const float* __restrict__ dl_wih, const float* __restrict__ dl_whh,
                            const float* __restrict__ dl_b,
                            const float* __restrict__ da1w) {
    int stride = gridDim.x * blockDim.x;
    int idx0 = blockIdx.x * blockDim.x + threadIdx.x;
    // Encoder (layer 2 only): k order = [x 0..95 (81 real) | h 0..255]
    for (int i = idx0; i < KENC_PAD * NG; i += stride) {
        int k = i >> 10, col = i & 1023;
        int n = lstm_src_n(col);
        float v = 0.f;
        if (k < D)        v = l2_wih[n * D + k];
        else if (k >= XP) v = l2_whh[n * HE + (k - XP)];
        g_Wenc16[frag16_idx(k, col, 16)] = __float2half_rn(v);
    }
    // Decoder: k order = [d 0..255]
    for (int i = idx0; i < KDEC_PAD * NG; i += stride) {
        int k = i >> 10, col = i & 1023;
        int n = lstm_src_n(col);
        g_Wdec16[frag16_idx(k, col, 16)] = __float2half_rn(dl_whh[n * HE + k]);
    }
    for (int i = idx0; i < 512 * HE; i += stride) {
        int k = i >> 8, n = i & 255;
        float v = (k < HE) ? da1w[n * 768 + k] : da1w[n * 768 + 256 + (k - HE)];
        g_Wq16[frag16_idx(k, n, 4)] = __float2half_rn(v);
    }
    for (int i = idx0; i < HE * HE; i += stride) {
        int k = i >> 8, n = i & 255;
        g_Wxp16[frag16_idx(k, n, 4)] = __float2half_rn(da1w[n * 768 + 512 + k]);
    }
    for (int i = idx0; i < NG; i += stride) {
        int n = lstm_src_n(i);
        g_benc[i] = l2_b[n];
        g_bdec[i] = dl_b[n];
        g_wyt[i]  = dl_wih[n];
    }
}

__global__ void init_kernel() {
    int stride = gridDim.x * blockDim.x;
    int i0 = blockIdx.x * blockDim.x + threadIdx.x;
    __half hz = __float2half_rn(0.f);
    for (int j = i0; j < B * HE; j += stride) {
        g_h16[0][j] = hz;
        g_c2[0][j] = 0.f;
    }
    for (int j = i0; j < B * 512; j += stride) {
        g_dc[0][j] = 0.f;
        g_dc16[0][j] = hz;
    }
}

// ------- input attention (a1*a2) + fused scaled-X production --------------
__global__ void attn_kernel(const float* __restrict__ X, const float* __restrict__ yprev,
                            const float* __restrict__ e1w, const float* __restrict__ e1b,
                            const float* __restrict__ e2w, const float* __restrict__ e2b) {
    int b = blockIdx.x;
    int j = threadIdx.x;
    float v1 = -1e30f, v2 = -1e30f;
    float xv[T];
    if (j < D) {
        const float* xb = X + (size_t)b * T * D + j;
        float s1 = 0.f, s2 = 0.f;
#pragma unroll
        for (int t = 0; t < T; ++t) {
            float x = xb[t * D];
            xv[t] = x;
            s1 += x * e1w[2 * HE + t];
            s2 += x * e2w[2 * HE + t];
        }
        float yw = 0.f;
#pragma unroll
        for (int t = 0; t < T; ++t) yw += yprev[b * T + t] * e2w[2 * HE + T + t];
        v1 = s1 + e1b[0];
        v2 = s2 + yw + e2b[0];
    }
    __shared__ float red1[128], red2[128];
    red1[j] = v1; red2[j] = v2;
    __syncthreads();
    for (int o = 64; o > 0; o >>= 1) {
        if (j < o) {
            red1[j] = fmaxf(red1[j], red1[j + o]);
            red2[j] = fmaxf(red2[j], red2[j + o]);
        }
        __syncthreads();
    }
    float m1 = red1[0], m2 = red2[0];
    __syncthreads();
    float e1v = (j < D) ? __expf(v1 - m1) : 0.f;
    float e2v = (j < D) ? __expf(v2 - m2) : 0.f;
    red1[j] = e1v; red2[j] = e2v;
    __syncthreads();
    for (int o = 64; o > 0; o >>= 1) {
        if (j < o) { red1[j] += red1[j + o]; red2[j] += red2[j + o]; }
        __syncthreads();
    }
    float a12 = 0.f;
    if (j < D)
        a12 = __fdividef(e1v, red1[0]) * __fdividef(e2v, red2[0]);
    if (j < XP) {
        __half hz = __float2half_rn(0.f);
#pragma unroll
        for (int t = 0; t < T; ++t) {
            __half val = (j < D) ? __float2half_rn(a12 * xv[t]) : hz;
            g_Xs16[(size_t)t * B * XP + b * XP + j] = val;
        }
    }
}

// ============= fp16 tensor-core GEMM + fused LSTM epilogue =================
// MODE 0: encoder step (layer 2 only); MODE 1: decoder LSTM
template <int MODE>
__global__ __launch_bounds__(256) void lstm_mma_kernel(int t, int pin, int pout) {
    const __half* xsrc = nullptr;
    const __half* h16in = nullptr;
    const float* cin = nullptr;
    __half* h16out = nullptr;
    float* cout = nullptr;
    const __half* Wg;
    const float* bias;
    const float* dcin = nullptr;
    float* dcout = nullptr;
    const __half* d16in = nullptr;
    __half* d16out = nullptr;
    int NC;
    if (MODE == 0) {
        xsrc = &g_Xs16[(size_t)t * B * XP];
        h16in = g_h16[pin];
        h16out = g_h16[pout];
        cin = g_c2[pin];
        cout = g_c2[pout];
        Wg = g_Wenc16;
        bias = g_benc;
        NC = KENC_PAD / BK;      // 22
    } else {
        dcin = g_dc[pin];
        dcout = g_dc[pout];
        d16in = g_dc16[pin];
        d16out = g_dc16[pout];
        Wg = g_Wdec16;
        bias = g_bdec;
        NC = KDEC_PAD / BK;      // 16
    }

    __shared__ __align__(16) unsigned Asw[2][AS32];
    __shared__ __align__(16) unsigned Bsw[2][BS32];

    int tid = threadIdx.x;
    int lane = tid & 31;
    int wid = tid >> 5;
    int wm = wid & 3, wn = wid >> 2;      // 4 row-warps x 2 col-warps (64 cols each)
    int lq = lane & 3, lr = lane >> 2;
    int row0 = blockIdx.x * BM;
    int col0 = blockIdx.y * BN;
    int cg = col0 >> 6;                   // even

    // A loader: thread = (row, k-half); loads 8 consecutive halves (int4)
    int arow = tid >> 1;
    int akf = tid & 1;
    int agb = row0 + arow;
    int rt = arow & 15, mt = arow >> 4;
    int r = rt & 7, rhalf = rt >> 3;
    int abase = mt * 128 + akf * 2 + rhalf;

    const __half* xrow = (MODE == 0) ? (xsrc + (size_t)agb * XP) : nullptr;
    const __half* hrow = (MODE == 0) ? (h16in + (size_t)agb * HE) : (d16in + (size_t)agb * 512);
    const int4* wp4 = reinterpret_cast<const int4*>(Wg);

    float acc[2][8][4] = {};
    int4 av;
    int4 bv;

    auto loadChunk = [&](int kc) {
        if (MODE == 0) {
            const __half* p = (kc < 6) ? (xrow + kc * 16 + akf * 8)
                                       : (hrow + (kc - 6) * 16 + akf * 8);
            av = *(const int4*)p;
        } else {
            av = *(const int4*)(hrow + kc * 16 + akf * 8);
        }
        bv = wp4[((size_t)(kc * 16 + cg) << 7) + tid];
    };
    auto storeChunk = [&](int buf) {
        unsigned v[4] = {(unsigned)av.x, (unsigned)av.y, (unsigned)av.z, (unsigned)av.w};
        unsigned* as = Asw[buf];
#pragma unroll
        for (int j2 = 0; j2 < 4; ++j2)
            as[abase + (r * 4 + (j2 ^ (r >> 1))) * 4] = v[j2];
        *(int4*)&Bsw[buf][tid * 4] = bv;
    };
    auto compute = [&](int buf) {
        const unsigned* as = Asw[buf];
        const unsigned* bs = Bsw[buf];
        int aoff = (lr * 4 + (lq ^ (lr >> 1))) * 4;
        int4 af[2];
        int2 bf[8];
#pragma unroll
        for (int mi = 0; mi < 2; ++mi)
            af[mi] = *(const int4*)&as[(wm * 2 + mi) * 128 + aoff];
#pragma unroll
        for (int ni = 0; ni < 8; ++ni)
            bf[ni] = *(const int2*)&bs[(wn * 8 + ni) * 64 + lane * 2];
#pragma unroll
        for (int mi = 0; mi < 2; ++mi)
#pragma unroll
            for (int ni = 0; ni < 8; ++ni)
                mma_f16(acc[mi][ni], af[mi], bf[ni]);
    };

    loadChunk(0);
    storeChunk(0);
    __syncthreads();
#pragma unroll 1
    for (int kc = 0; kc < NC; ++kc) {
        int cur = kc & 1;
        if (kc + 1 < NC) loadChunk(kc + 1);
        compute(cur);
        if (kc + 1 < NC) storeChunk(cur ^ 1);
        __syncthreads();
    }

    // ---- fused LSTM epilogue on gate-interleaved columns ----
#pragma unroll
    for (int g32 = 0; g32 < 2; ++g32) {
        int cbase = col0 + wn * 64 + g32 * 32;
#pragma unroll
        for (int upair = 0; upair < 2; ++upair) {
            int unit = (cbase >> 2) + upair * 4 + lq;
            float bI = bias[cbase + upair * 8 + 2 * lq];
            float bF = bias[cbase + upair * 8 + 2 * lq + 1];
            float bG = bias[cbase + 16 + upair * 8 + 2 * lq];
            float bO = bias[cbase + 16 + upair * 8 + 2 * lq + 1];
            float wI = 0.f, wF = 0.f, wG = 0.f, wO = 0.f;
            if (MODE == 1) {
                wI = g_wyt[cbase + upair * 8 + 2 * lq];
                wF = g_wyt[cbase + upair * 8 + 2 * lq + 1];
                wG = g_wyt[cbase + 16 + upair * 8 + 2 * lq];
                wO = g_wyt[cbase + 16 + upair * 8 + 2 * lq + 1];
            }
            int niI = g32 * 4 + upair;      // i/f accumulator
            int niG = g32 * 4 + 2 + upair;  // g/o accumulator
#pragma unroll
            for (int mi = 0; mi < 2; ++mi) {
#pragma unroll
                for (int half = 0; half < 2; ++half) {
                    int gb = row0 + wm * 32 + mi * 16 + half * 8 + lr;
                    float gi = acc[mi][niI][half * 2 + 0] + bI;
                    float gf = acc[mi][niI][half * 2 + 1] + bF;
                    float gg = acc[mi][niG][half * 2 + 0] + bG;
                    float go = acc[mi][niG][half * 2 + 1] + bO;
                    float cold;
                    if (MODE == 0) {
                        cold = cin[gb * HE + unit];
                    } else {
                        float yv = __half2float(g_yt16[gb]);
                        gi += yv * wI; gf += yv * wF; gg += yv * wG; go += yv * wO;
                        cold = dcin[gb * 512 + 256 + unit];
                    }
                    float c2 = sigf(gf) * cold + sigf(gi) * ftanh(gg);
                    float h2 = sigf(go) * ftanh(c2);
                    if (MODE == 0) {
                        h16out[gb * HE + unit] = __float2half_rn(h2);
                        cout[gb * HE + unit] = c2;
                        g_Xenc16[((size_t)gb * T + t) * HE + unit] = __float2half_rn(h2);
                    } else {
                        dcout[gb * 512 + unit] = h2;
                        dcout[gb * 512 + 256 + unit] = c2;
                        d16out[gb * 512 + unit] = __float2half_rn(h2);
                        d16out[gb * 512 + 256 + unit] = __float2half_rn(c2);
                    }
                }
            }
        }
    }
}

// ---------------- fp16 plain GEMM, N=256 (xenc_proj and q) ----------------
// mode 0: xproj16 = Xenc @ Wxp + da1b  (M = B*T, K = 256), fp16 out
// mode 1: q       = [d|c] @ Wq         (M = B,   K = 512), fp32 out
__global__ __launch_bounds__(256) void gemm256_mma_kernel(int mode, int pin,
                                                          const float* __restrict__ bias) {
    const __half* Aptr;
    const __half* Wptr;
    int lda, NC;
    if (mode == 0) { Aptr = g_Xenc16;    Wptr = g_Wxp16; lda = 256; NC = 16; }
    else           { Aptr = g_dc16[pin]; Wptr = g_Wq16;  lda = 512; NC = 32; }

    __shared__ __align__(16) unsigned Asw[2][AS32];
    __shared__ __align__(16) unsigned Bsw[2][528];

    int tid = threadIdx.x;
    int lane = tid & 31;
    int wid = tid >> 5;
    int wm = wid & 3, wn = wid >> 2;
    int lq = lane & 3, lr = lane >> 2;
    int row0 = blockIdx.x * BM;
    int col0 = blockIdx.y * 64;
    int cg = col0 >> 6;

    int arow = tid >> 1;
    int akf = tid & 1;
    int rt = arow & 15, mt = arow >> 4;
    int r = rt & 7, rhalf = rt >> 3;
    int abase = mt * 128 + akf * 2 + rhalf;
    const __half* arowp = Aptr + (size_t)(row0 + arow) * lda + akf * 8;
    const int2* wp = reinterpret_cast<const int2*>(Wptr);

    float acc[2][4][4] = {};
    int4 av;
    int2 bv;

    auto loadChunk = [&](int kc) {
        av = *(const int4*)(arowp + kc * 16);
        bv = wp[((size_t)(kc * 4 + cg) << 8) + tid];
    };
    auto storeChunk = [&](int buf) {
        unsigned v[4] = {(unsigned)av.x, (unsigned)av.y, (unsigned)av.z, (unsigned)av.w};
        unsigned* as = Asw[buf];
#pragma unroll
        for (int j2 = 0; j2 < 4; ++j2)
            as[abase + (r * 4 + (j2 ^ (r >> 1))) * 4] = v[j2];
        *(int2*)&Bsw[buf][tid * 2] = bv;
    };
    auto compute = [&](int buf) {
        const unsigned* as = Asw[buf];
        const unsigned* bs = Bsw[buf];
        int aoff = (lr * 4 + (lq ^ (lr >> 1))) * 4;
        int4 af[2];
        int2 bf[4];
#pragma unroll
        for (int mi = 0; mi < 2; ++mi)
            af[mi] = *(const int4*)&as[(wm * 2 + mi) * 128 + aoff];
#pragma unroll
        for (int ni = 0; ni < 4; ++ni)
            bf[ni] = *(const int2*)&bs[(wn * 4 + ni) * 64 + lane * 2];
#pragma unroll
        for (int mi = 0; mi < 2; ++mi)
#pragma unroll
            for (int ni = 0; ni < 4; ++ni)
                mma_f16(acc[mi][ni], af[mi], bf[ni]);
    };

    loadChunk(0);
    storeChunk(0);
    __syncthreads();
#pragma unroll 1
    for (int kc = 0; kc < NC; ++kc) {
        int cur = kc & 1;
        if (kc + 1 < NC) loadChunk(kc + 1);
        compute(cur);
        if (kc + 1 < NC) storeChunk(cur ^ 1);
        __syncthreads();
    }

#pragma unroll
    for (int mi = 0; mi < 2; ++mi) {
#pragma unroll
        for (int half = 0; half < 2; ++half) {
            int gb = row0 + wm * 32 + mi * 16 + half * 8 + lr;
#pragma unroll
            for (int ni = 0; ni < 4; ++ni) {
                int col = col0 + wn * 32 + ni * 8 + 2 * lq;
                float v0 = acc[mi][ni][half * 2 + 0] + (bias ? bias[col] : 0.f);
                float v1 = acc[mi][ni][half * 2 + 1] + (bias ? bias[col + 1] : 0.f);
                if (mode == 0) {
                    __half2 hv = __floats2half2_rn(v0, v1);
                    *(__half2*)&g_xproj16[(size_t)gb * HE + col] = hv;
                } else {
                    *(float2*)&g_q[(size_t)gb * HE + col] = make_float2(v0, v1);
                }
            }
        }
    }
}

// ---------------- decoder attention (row-wise fused, fp16 streams) --------
__global__ __launch_bounds__(256) void dec_attn_kernel(const float* __restrict__ yprev,
                                                       const float* __restrict__ a2w,
                                                       const float* __restrict__ a2b,
                                                       const float* __restrict__ fcw,
                                                       const float* __restrict__ fcb, int t) {
    int b = blockIdx.x;
    int h = threadIdx.x;
    float qh = g_q[b * HE + h];
    float w = a2w[h];
    const __half* xp = g_xproj16 + (size_t)(b * T) * HE + h;
    float sloc[T];
#pragma unroll
    for (int tt = 0; tt < T; ++tt)
        sloc[tt] = ftanh(__half2float(xp[tt * HE]) + qh) * w;

    __shared__ float part[8][T];
    __shared__ float beta[T];
    int lane = h & 31, wid = h >> 5;
#pragma unroll
    for (int tt = 0; tt < T; ++tt) {
        float v = sloc[tt];
        for (int o = 16; o > 0; o >>= 1) v += __shfl_down_sync(0xFFFFFFFFu, v, o);
        if (!lane) part[wid][tt] = v;
    }
    __syncthreads();
    if (h == 0) {
        float sc[T];
        float mx = -1e30f;
#pragma unroll
        for (int tt = 0; tt < T; ++tt) {
            float s = a2b[0];
#pragma unroll
            for (int w8 = 0; w8 < 8; ++w8) s += part[w8][tt];
            sc[tt] = s;
            mx = fmaxf(mx, s);
        }
        float sum = 0.f;
#pragma unroll
        for (int tt = 0; tt < T; ++tt) { sc[tt] = __expf(sc[tt] - mx); sum += sc[tt]; }
        float inv = __fdividef(1.f, sum);
#pragma unroll
        for (int tt = 0; tt < T; ++tt) beta[tt] = sc[tt] * inv;
    }
    __syncthreads();
    const __half* xe = g_Xenc16 + (size_t)(b * T) * HE + h;
    float ctx = 0.f;
#pragma unroll
    for (int tt = 0; tt < T; ++tt) ctx += beta[tt] * __half2float(xe[tt * HE]);
    g_ctx[b * HE + h] = ctx;
    float yv = ctx * fcw[h];
    for (int o = 16; o > 0; o >>= 1) yv += __shfl_down_sync(0xFFFFFFFFu, yv, o);
    __syncthreads();
    if (!lane) part[wid][0] = yv;
    __syncthreads();
    if (h == 0) {
        float s = 0.f;
#pragma unroll
        for (int w8 = 0; w8 < 8; ++w8) s += part[w8][0];
        g_yt16[b] = __float2half_rn(s + yprev[b * T + t] * fcw[HE] + fcb[0]);
    }
}

// ---------------- final output --------------------------------------------
__global__ void final_kernel(const float* __restrict__ ffw, const float* __restrict__ ffb,
                             float* __restrict__ out, int pin) {
    int gtid = blockIdx.x * blockDim.x + threadIdx.x;
    int warp = gtid >> 5;
    int lane = gtid & 31;
    if (warp >= B) return;
    const float* d = g_dc[pin] + warp * 512;
    const float* ctx = g_ctx + warp * HE;
    float s = 0.f;
    for (int h = lane; h < HE; h += 32) s += d[h] * ffw[h] + ctx[h] * ffw[HE + h];
    for (int o = 16; o > 0; o >>= 1) s += __shfl_down_sync(0xFFFFFFFFu, s, o);
    if (!lane) out[warp] = s + ffb[0];
}

// ---------------- launch ---------------------------------------------------
extern "C" void kernel_launch(void* const* d_in, const int* in_sizes, int n_in,
                              void* d_out, int out_size) {
    const float* X      = (const float*)d_in[0];
    const float* yprev  = (const float*)d_in[1];
    const float* e1w    = (const float*)d_in[2];
    const float* e1b    = (const float*)d_in[3];
    const float* e2w    = (const float*)d_in[4];
    const float* e2b    = (const float*)d_in[5];
    const float* l2_wih = (const float*)d_in[9];
    const float* l2_whh = (const float*)d_in[10];
    const float* l2_b   = (const float*)d_in[11];
    const float* da1w   = (const float*)d_in[12];
    const float* da1b   = (const float*)d_in[13];
    const float* da2w   = (const float*)d_in[14];
    const float* da2b   = (const float*)d_in[15];
    const float* dlwih  = (const float*)d_in[16];
    const float* dlwhh  = (const float*)d_in[17];
    const float* dlb    = (const float*)d_in[18];
    const float* fcw    = (const float*)d_in[19];
    const float* fcb    = (const float*)d_in[20];
    const float* ffw    = (const float*)d_in[21];
    const float* ffb    = (const float*)d_in[22];
    float* out = (float*)d_out;

    pack_kernel<<<512, 256>>>(l2_wih, l2_whh, l2_b, dlwih, dlwhh, dlb, da1w);
    init_kernel<<<512, 256>>>();
    attn_kernel<<<B, 128>>>(X, yprev, e1w, e1b, e2w, e2b);

    for (int t = 0; t < T; ++t)
        lstm_mma_kernel<0><<<dim3(B / BM, NG / BN), 256>>>(t, t & 1, (t + 1) & 1);

    // xenc_proj over all (b, t)
    gemm256_mma_kernel<<<dim3(B * T / BM, HE / 64), 256>>>(0, 0, da1b);

    for (int t = 0; t < T; ++t) {
        gemm256_mma_kernel<<<dim3(B / BM, HE / 64), 256>>>(1, t & 1, nullptr);
        dec_attn_kernel<<<B, 256>>>(yprev, da2w, da2b, fcw, fcb, t);
        lstm_mma_kernel<1><<<dim3(B / BM, NG / BN), 256>>>(0, t & 1, (t + 1) & 1);
    }

    final_kernel<<<B * 32 / 256, 256>>>(ffw, ffb, out, T & 1);
}